// round 12
// baseline (speedup 1.0000x reference)
#include <cuda_runtime.h>
#include <cuda_fp16.h>
#include <math_constants.h>
#include <cstdint>

#define N_ROWS 8192
#define DIM    1024
#define NCLS   1000

// ---- fp16 mma.sync GEMM tile config: BM=128, BN=256, 8 warps of 64x64 ----
#define BM 128
#define BN 256
#define BKH 64                                   // halves per K-chunk (128B row)
#define STAGES 3
#define A_TILE_WORDS (BM * BKH / 2)              // 4096 words (16KB)
#define B_TILE_WORDS (BN * BKH / 2)              // 8192 words (32KB)
#define STAGE_WORDS  (A_TILE_WORDS + B_TILE_WORDS)
#define DYN_SMEM     (STAGES * STAGE_WORDS * 4)  // 144KB -> 1 CTA/SM

// ---------------- scratch (device globals: allocation-free) ----------------
__device__ __half g_xh [N_ROWS * DIM];
__device__ __half g_qh [N_ROWS * DIM];
__device__ __half g_kh [N_ROWS * DIM];
__device__ float  g_xr [N_ROWS * DIM];
__device__ float  g_a  [N_ROWS * DIM];
__device__ __half g_mh [N_ROWS * DIM];
__device__ __half g_vTh[DIM * N_ROWS];
__device__ __half g_Sh [(size_t)N_ROWS * N_ROWS];   // 128 MB fp16 scores
__device__ __half g_WcatT[4 * DIM * DIM];           // concat(Wq^T|Wk^T|Wv^T|Ws^T)
__device__ __half g_WfcT [NCLS * DIM];

// ================= helpers =================
__device__ __forceinline__ uint32_t smem_u32(const void* p) {
    uint32_t a;
    asm("{ .reg .u64 t; cvta.to.shared.u64 t, %1; cvt.u32.u64 %0, t; }" : "=r"(a) : "l"(p));
    return a;
}
__device__ __forceinline__ int swzw(int r, int w) {
    return r * 32 + (w ^ ((r & 7) << 2));
}
__device__ __forceinline__ void cp16(uint32_t saddr, const void* g) {
    asm volatile("cp.async.cg.shared.global [%0], [%1], 16;" :: "r"(saddr), "l"(g));
}
__device__ __forceinline__ void cp16z(uint32_t saddr, const void* g, int valid) {
    int sz = valid ? 16 : 0;
    asm volatile("cp.async.cg.shared.global [%0], [%1], 16, %2;" :: "r"(saddr), "l"(g), "r"(sz));
}
__device__ __forceinline__ void ldsm4(uint32_t& r0, uint32_t& r1, uint32_t& r2, uint32_t& r3,
                                      uint32_t addr) {
    asm volatile("ldmatrix.sync.aligned.m8n8.x4.shared.b16 {%0,%1,%2,%3}, [%4];"
                 : "=r"(r0), "=r"(r1), "=r"(r2), "=r"(r3) : "r"(addr));
}
__device__ __forceinline__ void mma_f16(float& d0, float& d1, float& d2, float& d3,
                                        uint32_t a0, uint32_t a1, uint32_t a2, uint32_t a3,
                                        uint32_t b0, uint32_t b1) {
    asm volatile(
        "mma.sync.aligned.m16n8k16.row.col.f32.f16.f16.f32 "
        "{%0,%1,%2,%3}, {%4,%5,%6,%7}, {%8,%9}, {%0,%1,%2,%3};"
        : "+f"(d0), "+f"(d1), "+f"(d2), "+f"(d3)
        : "r"(a0), "r"(a1), "r"(a2), "r"(a3), "r"(b0), "r"(b1));
}

// ---- 256-thread CTA, 8 warps in 2(M) x 4(N), 64x64 warp tiles, frag double-buffer ----

#define PREFETCH(T, SLOT) do {                                                     \
        const uint32_t _sa = smem_base + (SLOT) * STAGE_WORDS * 4;                 \
        const uint32_t _sb = _sa + A_TILE_WORDS * 4;                               \
        const int _k0 = (T) * BKH;                                                 \
        _Pragma("unroll")                                                          \
        for (int i = 0; i < 4; i++) {                                              \
            const int r = lr + i * 32;                                             \
            cp16(_sa + swzw(r, lc * 4) * 4, Ag + (size_t)i * 32 * K + _k0);        \
        }                                                                          \
        _Pragma("unroll")                                                          \
        for (int i = 0; i < 8; i++) {                                              \
            const int r = lr + i * 32;                                             \
            const int gr = nbase + r;                                              \
            const int vld = gr < Nb;                                               \
            const __half* bp = B + (size_t)(vld ? gr : 0) * K + _k0 + lc * 8;      \
            cp16z(_sb + swzw(r, lc * 4) * 4, bp, vld);                             \
        }                                                                          \
    } while (0)

#define LOAD_FRAGS(BUF, KS) do {                                                   \
        const uint32_t _ac = (uint32_t)((2 * (KS) + aCoff) << 4);                  \
        const uint32_t _bc = (uint32_t)((2 * (KS) + bCoff) << 4);                  \
        _Pragma("unroll")                                                          \
        for (int mf = 0; mf < 4; mf++)                                             \
            ldsm4(af[BUF][mf][0], af[BUF][mf][1], af[BUF][mf][2], af[BUF][mf][3],  \
                  sa + aOff[mf] + (_ac ^ aXr[mf]));                                \
        _Pragma("unroll")                                                          \
        for (int p = 0; p < 4; p++)                                                \
            ldsm4(bf[BUF][2 * p][0], bf[BUF][2 * p][1],                            \
                  bf[BUF][2 * p + 1][0], bf[BUF][2 * p + 1][1],                    \
                  sb + bOff[p] + (_bc ^ bXr[p]));                                  \
    } while (0)

#define GEMM_MAINLOOP()                                                            \
    const int lr = tid >> 3;                                                       \
    const int lc = tid & 7;                                                        \
    const __half* Ag = A + (size_t)(mbase + lr) * K + lc * 8;                      \
    const uint32_t smem_base = smem_u32(sm32);                                     \
    const int aRowL = lane & 15;                                                   \
    const int aCoff = lane >> 4;                                                   \
    uint32_t aOff[4], aXr[4];                                                      \
    _Pragma("unroll")                                                              \
    for (int mf = 0; mf < 4; mf++) {                                               \
        const int r = warpM * 64 + mf * 16 + aRowL;                                \
        aOff[mf] = (uint32_t)r * 128;                                              \
        aXr[mf]  = (uint32_t)((r & 7) << 4);                                       \
    }                                                                              \
    const int bRowL = ((lane >> 4) << 3) + (lane & 7);                             \
    const int bCoff = (lane >> 3) & 1;                                             \
    uint32_t bOff[4], bXr[4];                                                      \
    _Pragma("unroll")                                                              \
    for (int p = 0; p < 4; p++) {                                                  \
        const int r = warpN * 64 + p * 16 + bRowL;                                 \
        bOff[p] = (uint32_t)r * 128;                                               \
        bXr[p]  = (uint32_t)((r & 7) << 4);                                        \
    }                                                                              \
    _Pragma("unroll")                                                              \
    for (int mf = 0; mf < 4; mf++)                                                 \
        _Pragma("unroll")                                                          \
        for (int nf = 0; nf < 8; nf++)                                             \
            _Pragma("unroll")                                                      \
            for (int rr = 0; rr < 4; rr++) acc[mf][nf][rr] = 0.f;                  \
    const int Kc = K / BKH;                                                        \
    PREFETCH(0, 0);                                                                \
    asm volatile("cp.async.commit_group;");                                        \
    if (Kc > 1) PREFETCH(1, 1);                                                    \
    asm volatile("cp.async.commit_group;");                                        \
    uint32_t af[2][4][4], bf[2][8][2];                                             \
    for (int t = 0; t < Kc; t++) {                                                 \
        asm volatile("cp.async.wait_group 1;");                                    \
        __syncthreads();                                                           \
        if (t + 2 < Kc) PREFETCH(t + 2, (t + 2) % STAGES);                         \
        asm volatile("cp.async.commit_group;");                                    \
        const uint32_t sa = smem_base + (t % STAGES) * STAGE_WORDS * 4;            \
        const uint32_t sb = sa + A_TILE_WORDS * 4;                                 \
        LOAD_FRAGS(0, 0);                                                          \
        _Pragma("unroll")                                                          \
        for (int ks = 0; ks < 4; ks++) {                                           \
            const int cur = ks & 1;                                                \
            if (ks < 3) LOAD_FRAGS(cur ^ 1, ks + 1);                               \
            _Pragma("unroll")                                                      \
            for (int mf = 0; mf < 4; mf++)                                         \
                _Pragma("unroll")                                                  \
                for (int nf = 0; nf < 8; nf++)                                     \
                    mma_f16(acc[mf][nf][0], acc[mf][nf][1], acc[mf][nf][2], acc[mf][nf][3], \
                            af[cur][mf][0], af[cur][mf][1], af[cur][mf][2], af[cur][mf][3], \
                            bf[cur][nf][0], bf[cur][nf][1]);                       \
        }                                                                          \
        __syncthreads();                                                           \
    }

// =============== generic fp16 mma GEMM: C = scale*(A @ B^T) + bias ===============
// grid = (ceil(Ncols/BN), M/BM), block = 256
__global__ void __launch_bounds__(256)
gemm_h(const __half* __restrict__ A, const __half* __restrict__ B,
       const float* __restrict__ bias, void* __restrict__ Cv,
       int out_half, float scale, int Ncols, int Nb, int K, int ldc)
{
    extern __shared__ uint32_t sm32[];
    const int tid  = threadIdx.x;
    const int wid  = tid >> 5;
    const int lane = tid & 31;
    const int gid  = lane >> 2;
    const int tig  = lane & 3;
    const int warpM = wid & 1;
    const int warpN = wid >> 1;                 // 0..3
    const int mbase = blockIdx.y * BM;
    const int nbase = blockIdx.x * BN;

    float acc[4][8][4];
    GEMM_MAINLOOP()

    float* Cf = (float*)Cv;
    __half* Ch = (__half*)Cv;
    #pragma unroll
    for (int mf = 0; mf < 4; mf++) {
        const int r0 = mbase + warpM * 64 + mf * 16 + gid;
        #pragma unroll
        for (int nf = 0; nf < 8; nf++) {
            const int col = nbase + warpN * 64 + nf * 8 + tig * 2;
            float v0 = acc[mf][nf][0] * scale;
            float v1 = acc[mf][nf][1] * scale;
            float v2 = acc[mf][nf][2] * scale;
            float v3 = acc[mf][nf][3] * scale;
            if (bias) {
                const float bz0 = (col < Ncols) ? __ldg(bias + col) : 0.f;
                const float bz1 = (col + 1 < Ncols) ? __ldg(bias + col + 1) : 0.f;
                v0 += bz0; v1 += bz1; v2 += bz0; v3 += bz1;
            }
            if (out_half) {
                if (col + 1 < Ncols) {
                    *(__half2*)(Ch + (size_t)r0 * ldc + col)       = __floats2half2_rn(v0, v1);
                    *(__half2*)(Ch + (size_t)(r0 + 8) * ldc + col) = __floats2half2_rn(v2, v3);
                } else if (col < Ncols) {
                    Ch[(size_t)r0 * ldc + col]       = __float2half_rn(v0);
                    Ch[(size_t)(r0 + 8) * ldc + col] = __float2half_rn(v2);
                }
            } else {
                if (col + 1 < Ncols) {
                    *(float2*)(Cf + (size_t)r0 * ldc + col)       = make_float2(v0, v1);
                    *(float2*)(Cf + (size_t)(r0 + 8) * ldc + col) = make_float2(v2, v3);
                } else if (col < Ncols) {
                    Cf[(size_t)r0 * ldc + col]       = v0;
                    Cf[(size_t)(r0 + 8) * ldc + col] = v2;
                }
            }
        }
    }
}

// =============== fused 4-way projection GEMM ===============
// B = concat(Wq^T|Wk^T|Wv^T|Ws^T) [4096 x 1024]; each CTA's BN=256 cols in one segment.
// seg 0 -> qh fp16, 1 -> kh fp16, 2 -> vTh fp16 TRANSPOSED [DIM x N_ROWS], 3 -> xr fp32.
__global__ void __launch_bounds__(256)
gemm_proj4(const __half* __restrict__ A, const __half* __restrict__ B,
           const float* __restrict__ bq, const float* __restrict__ bk,
           const float* __restrict__ bv, const float* __restrict__ bs,
           __half* __restrict__ oq, __half* __restrict__ ok,
           __half* __restrict__ ovT, float* __restrict__ oxr,
           int Nb, int K)
{
    extern __shared__ uint32_t sm32[];
    const int tid  = threadIdx.x;
    const int wid  = tid >> 5;
    const int lane = tid & 31;
    const int gid  = lane >> 2;
    const int tig  = lane & 3;
    const int warpM = wid & 1;
    const int warpN = wid >> 1;
    const int mbase = blockIdx.y * BM;
    const int nbase = blockIdx.x * BN;

    float acc[4][8][4];
    GEMM_MAINLOOP()

    const int seg = nbase >> 10;                 // 0..3
    const float* bias = (seg == 0) ? bq : (seg == 1) ? bk : (seg == 2) ? bv : bs;

    #pragma unroll
    for (int mf = 0; mf < 4; mf++) {
        const int r0 = mbase + warpM * 64 + mf * 16 + gid;
        #pragma unroll
        for (int nf = 0; nf < 8; nf++) {
            const int col = nbase + warpN * 64 + nf * 8 + tig * 2;
            const int cl = col & (DIM - 1);      // column within segment
            const float bz0 = __ldg(bias + cl);
            const float bz1 = __ldg(bias + cl + 1);
            const float v0 = acc[mf][nf][0] + bz0;
            const float v1 = acc[mf][nf][1] + bz1;
            const float v2 = acc[mf][nf][2] + bz0;
            const float v3 = acc[mf][nf][3] + bz1;
            if (seg == 0 || seg == 1) {
                __half* Ch = (seg == 0) ? oq : ok;
                *(__half2*)(Ch + (size_t)r0 * DIM + cl)       = __floats2half2_rn(v0, v1);
                *(__half2*)(Ch + (size_t)(r0 + 8) * DIM + cl) = __floats2half2_rn(v2, v3);
            } else if (seg == 2) {
                // write v transposed: vT[cl][row]
                ovT[(size_t)cl * N_ROWS + r0]           = __float2half_rn(v0);
                ovT[(size_t)(cl + 1) * N_ROWS + r0]     = __float2half_rn(v1);
                ovT[(size_t)cl * N_ROWS + r0 + 8]       = __float2half_rn(v2);
                ovT[(size_t)(cl + 1) * N_ROWS + r0 + 8] = __float2half_rn(v3);
            } else {
                *(float2*)(oxr + (size_t)r0 * DIM + cl)       = make_float2(v0, v1);
                *(float2*)(oxr + (size_t)(r0 + 8) * DIM + cl) = make_float2(v2, v3);
            }
        }
    }
}

// =============== x -> fp16 copy ===============
__global__ void __launch_bounds__(256)
half_copy(const float* __restrict__ in, __half* __restrict__ out, int n8)
{
    int i = blockIdx.x * 256 + threadIdx.x;
    if (i < n8) {
        float4 f0 = ((const float4*)in)[2 * i];
        float4 f1 = ((const float4*)in)[2 * i + 1];
        __half2 h0 = __floats2half2_rn(f0.x, f0.y);
        __half2 h1 = __floats2half2_rn(f0.z, f0.w);
        __half2 h2 = __floats2half2_rn(f1.x, f1.y);
        __half2 h3 = __floats2half2_rn(f1.z, f1.w);
        uint4 o;
        o.x = *(uint32_t*)&h0; o.y = *(uint32_t*)&h1;
        o.z = *(uint32_t*)&h2; o.w = *(uint32_t*)&h3;
        ((uint4*)out)[i] = o;
    }
}

// =============== transpose fp32 -> fp16: out[C,R] = half(in[R,C]^T) ===============
__global__ void __launch_bounds__(256)
transpose_h(const float* __restrict__ in, __half* __restrict__ out, int R, int C)
{
    __shared__ float t[32][33];
    const int bx = blockIdx.x * 32, by = blockIdx.y * 32;
    const int txx = threadIdx.x, tyy = threadIdx.y;
    #pragma unroll
    for (int i = tyy; i < 32; i += 8) {
        int y = by + i, x = bx + txx;
        if (y < R && x < C) t[i][txx] = in[(size_t)y * C + x];
    }
    __syncthreads();
    #pragma unroll
    for (int i = tyy; i < 32; i += 8) {
        int oy = bx + i, ox = by + txx;
        if (oy < C && ox < R) out[(size_t)oy * R + ox] = __float2half_rn(t[txx][i]);
    }
}

// =============== single-pass row softmax over 8192 fp16 cols ===============
__global__ void __launch_bounds__(256)
softmax_h(__half* __restrict__ S)
{
    const int row = blockIdx.x;
    __half2* p = (__half2*)(S + (size_t)row * N_ROWS);
    const int tid = threadIdx.x;

    float2 v[16];
    float mx = -CUDART_INF_F;
    #pragma unroll
    for (int i = 0; i < 16; i++) {
        v[i] = __half22float2(p[tid + i * 256]);
        mx = fmaxf(mx, fmaxf(v[i].x, v[i].y));
    }
    __shared__ float red[8];
    #pragma unroll
    for (int o = 16; o > 0; o >>= 1) mx = fmaxf(mx, __shfl_xor_sync(0xffffffffu, mx, o));
    if ((tid & 31) == 0) red[tid >> 5] = mx;
    __syncthreads();
    if (tid < 8) {
        float m = red[tid];
        #pragma unroll
        for (int o = 4; o > 0; o >>= 1) m = fmaxf(m, __shfl_xor_sync(0xffu, m, o));
        if (tid == 0) red[0] = m;
    }
    __syncthreads();
    mx = red[0];
    __syncthreads();

    float sum = 0.f;
    #pragma unroll
    for (int i = 0; i < 16; i++) {
        v[i].x = __expf(v[i].x - mx);
        v[i].y = __expf(v[i].y - mx);
        sum += v[i].x + v[i].y;
    }
    #pragma unroll
    for (int o = 16; o > 0; o >>= 1) sum += __shfl_xor_sync(0xffffffffu, sum, o);
    if ((tid & 31) == 0) red[tid >> 5] = sum;
    __syncthreads();
    if (tid < 8) {
        float s = red[tid];
        #pragma unroll
        for (int o = 4; o > 0; o >>= 1) s += __shfl_xor_sync(0xffu, s, o);
        if (tid == 0) red[0] = s;
    }
    __syncthreads();
    const float inv = 1.f / red[0];
    #pragma unroll
    for (int i = 0; i < 16; i++)
        p[tid + i * 256] = __floats2half2_rn(v[i].x * inv, v[i].y * inv);
}

// =============== beta gate + mix -> fp16 m, one block per row ===============
__global__ void __launch_bounds__(256)
beta_mix(const float* __restrict__ a, const float* __restrict__ xr,
         const float* __restrict__ Wb, const float* __restrict__ bb,
         __half* __restrict__ Mout)
{
    const int row = blockIdx.x;
    const int tid = threadIdx.x;
    const float* ap = a  + (size_t)row * DIM;
    const float* xp = xr + (size_t)row * DIM;

    float partial = 0.f;
    #pragma unroll
    for (int i = tid; i < DIM; i += 256) {
        float av = ap[i], xv = xp[i];
        partial += av * Wb[i] + xv * Wb[DIM + i] + (av - xv) * Wb[2 * DIM + i];
    }
    __shared__ float red[8];
    #pragma unroll
    for (int o = 16; o > 0; o >>= 1) partial += __shfl_xor_sync(0xffffffffu, partial, o);
    if ((tid & 31) == 0) red[tid >> 5] = partial;
    __syncthreads();
    __shared__ float s_beta;
    if (tid == 0) {
        float t = 0.f;
        #pragma unroll
        for (int w = 0; w < 8; w++) t += red[w];
        t += bb[0];
        s_beta = 1.f / (1.f + expf(-t));
    }
    __syncthreads();
    const float beta = s_beta;
    __half* mp = Mout + (size_t)row * DIM;
    #pragma unroll
    for (int i = tid; i < DIM; i += 256)
        mp[i] = __float2half_rn(beta * xp[i] + (1.f - beta) * ap[i]);
}

// =============== launch ===============
extern "C" void kernel_launch(void* const* d_in, const int* in_sizes, int n_in,
                              void* d_out, int out_size)
{
    const float* x      = (const float*)d_in[0];
    const float* W_skip = (const float*)d_in[1];
    const float* b_skip = (const float*)d_in[2];
    const float* W_q    = (const float*)d_in[3];
    const float* b_q    = (const float*)d_in[4];
    const float* W_k    = (const float*)d_in[5];
    const float* b_k    = (const float*)d_in[6];
    const float* W_v    = (const float*)d_in[7];
    const float* b_v    = (const float*)d_in[8];
    const float* W_beta = (const float*)d_in[9];
    const float* b_beta = (const float*)d_in[10];
    const float* W_fc   = (const float*)d_in[11];
    const float* b_fc   = (const float*)d_in[12];
    float* out = (float*)d_out;

    __half *xh, *qh, *kh, *mh, *vTh, *Sh, *WcatT, *WfcT;
    float *xr, *a;
    cudaGetSymbolAddress((void**)&xh,  g_xh);
    cudaGetSymbolAddress((void**)&qh,  g_qh);
    cudaGetSymbolAddress((void**)&kh,  g_kh);
    cudaGetSymbolAddress((void**)&xr,  g_xr);
    cudaGetSymbolAddress((void**)&a,   g_a);
    cudaGetSymbolAddress((void**)&mh,  g_mh);
    cudaGetSymbolAddress((void**)&vTh, g_vTh);
    cudaGetSymbolAddress((void**)&Sh,  g_Sh);
    cudaGetSymbolAddress((void**)&WcatT, g_WcatT);
    cudaGetSymbolAddress((void**)&WfcT,  g_WfcT);

    cudaFuncSetAttribute(gemm_h,     cudaFuncAttributeMaxDynamicSharedMemorySize, DYN_SMEM);
    cudaFuncSetAttribute(gemm_proj4, cudaFuncAttributeMaxDynamicSharedMemorySize, DYN_SMEM);

    const dim3 tb(32, 8);
    const dim3 blk(256);
    const dim3 gProj4(4 * DIM / BN, N_ROWS / BM);       // (16, 64)
    const dim3 gAv(DIM / BN, N_ROWS / BM);              // (4, 64)
    const dim3 gScore(N_ROWS / BN, N_ROWS / BM);        // (32, 64)
    const dim3 gFc((NCLS + BN - 1) / BN, N_ROWS / BM);  // (4, 64)

    // launch order: ncu (-s 5 -c 1) captures the fused projection GEMM
    half_copy<<<(N_ROWS * DIM / 8 + 255) / 256, 256>>>(x, xh, N_ROWS * DIM / 8);      // 0
    transpose_h<<<dim3(32, 32), tb>>>(W_q,    WcatT,                 DIM, DIM);       // 1
    transpose_h<<<dim3(32, 32), tb>>>(W_k,    WcatT + DIM * DIM,     DIM, DIM);       // 2
    transpose_h<<<dim3(32, 32), tb>>>(W_v,    WcatT + 2 * DIM * DIM, DIM, DIM);       // 3
    transpose_h<<<dim3(32, 32), tb>>>(W_skip, WcatT + 3 * DIM * DIM, DIM, DIM);       // 4
    gemm_proj4<<<gProj4, blk, DYN_SMEM>>>(xh, WcatT, b_q, b_k, b_v, b_skip,
                                          qh, kh, vTh, xr, 4 * DIM, DIM);             // 5 <- ncu
    gemm_h<<<gScore, blk, DYN_SMEM>>>(qh, kh, nullptr, Sh, 1, 1.f / 32.f,
                                      N_ROWS, N_ROWS, DIM, N_ROWS);
    transpose_h<<<dim3((NCLS + 31) / 32, 32), tb>>>(W_fc, WfcT, DIM, NCLS);

    softmax_h<<<N_ROWS, 256>>>(Sh);

    gemm_h<<<gAv, blk, DYN_SMEM>>>(Sh, vTh, nullptr, a, 0, 1.f, DIM, DIM, N_ROWS, DIM);

    beta_mix<<<N_ROWS, 256>>>(a, xr, W_beta, b_beta, mh);

    gemm_h<<<gFc, blk, DYN_SMEM>>>(mh, WfcT, b_fc, out, 0, 1.f, NCLS, NCLS, DIM, NCLS);
}

// round 13
// speedup vs baseline: 1.0958x; 1.0958x over previous
#include <cuda_runtime.h>
#include <cuda_fp16.h>
#include <math_constants.h>
#include <cstdint>

#define N_ROWS 8192
#define DIM    1024
#define NCLS   1000

// ---- fp16 mma.sync GEMM tile config (R10 proven config) ----
#define BM 128
#define BN 128
#define BKH 64                                  // halves per K-chunk (128B row)
#define STAGES 3
#define A_TILE_WORDS (BM * BKH / 2)             // 4096 32-bit words (16KB)
#define STAGE_WORDS  (2 * A_TILE_WORDS)         // 8192 words (32KB)
#define DYN_SMEM     (STAGES * STAGE_WORDS * 4) // 96KB -> 2 CTAs/SM

// ---------------- scratch (device globals: allocation-free) ----------------
__device__ __half g_xh [N_ROWS * DIM];
__device__ __half g_qh [N_ROWS * DIM];
__device__ __half g_kh [N_ROWS * DIM];
__device__ float  g_v  [N_ROWS * DIM];
__device__ float  g_xr [N_ROWS * DIM];
__device__ float  g_a  [N_ROWS * DIM];
__device__ __half g_mh [N_ROWS * DIM];
__device__ __half g_vTh[DIM * N_ROWS];
__device__ __half g_Sh [(size_t)N_ROWS * N_ROWS];   // 128 MB fp16 scores
__device__ __half g_WcatT[4 * DIM * DIM];           // concat(Wq^T|Wk^T|Wv^T|Ws^T)
__device__ __half g_WfcT [NCLS * DIM];

// ================= helpers =================
__device__ __forceinline__ uint32_t smem_u32(const void* p) {
    uint32_t a;
    asm("{ .reg .u64 t; cvta.to.shared.u64 t, %1; cvt.u32.u64 %0, t; }" : "=r"(a) : "l"(p));
    return a;
}
// word-granular XOR swizzle (16B-chunk granularity): (row r, word w) -> word offset
__device__ __forceinline__ int swzw(int r, int w) {
    return r * 32 + (w ^ ((r & 7) << 2));
}
__device__ __forceinline__ void cp16(uint32_t saddr, const void* g) {
    asm volatile("cp.async.cg.shared.global [%0], [%1], 16;" :: "r"(saddr), "l"(g));
}
__device__ __forceinline__ void cp16z(uint32_t saddr, const void* g, int valid) {
    int sz = valid ? 16 : 0;
    asm volatile("cp.async.cg.shared.global [%0], [%1], 16, %2;" :: "r"(saddr), "l"(g), "r"(sz));
}
__device__ __forceinline__ void ldsm4(uint32_t& r0, uint32_t& r1, uint32_t& r2, uint32_t& r3,
                                      uint32_t addr) {
    asm volatile("ldmatrix.sync.aligned.m8n8.x4.shared.b16 {%0,%1,%2,%3}, [%4];"
                 : "=r"(r0), "=r"(r1), "=r"(r2), "=r"(r3) : "r"(addr));
}
__device__ __forceinline__ void mma_f16(float& d0, float& d1, float& d2, float& d3,
                                        uint32_t a0, uint32_t a1, uint32_t a2, uint32_t a3,
                                        uint32_t b0, uint32_t b1) {
    asm volatile(
        "mma.sync.aligned.m16n8k16.row.col.f32.f16.f16.f32 "
        "{%0,%1,%2,%3}, {%4,%5,%6,%7}, {%8,%9}, {%0,%1,%2,%3};"
        : "+f"(d0), "+f"(d1), "+f"(d2), "+f"(d3)
        : "r"(a0), "r"(a1), "r"(a2), "r"(a3), "r"(b0), "r"(b1));
}

// ---- shared mainloop body (acc layout: [4][4][4], 64x32 warp tile) ----
#define GEMM_MAINLOOP()                                                            \
    const int lr = tid >> 3;                                                       \
    const int lc = tid & 7;                                                        \
    const __half* Ag = A + (size_t)(mbase + lr) * K + lc * 8;                      \
    const uint32_t smem_base = smem_u32(sm32);                                     \
    const int aRowL = lane & 15;                                                   \
    const int aCoff = lane >> 4;                                                   \
    uint32_t aOff[4], aXr[4];                                                      \
    _Pragma("unroll")                                                              \
    for (int mf = 0; mf < 4; mf++) {                                               \
        const int r = warpM * 64 + mf * 16 + aRowL;                                \
        aOff[mf] = (uint32_t)r * 128;                                              \
        aXr[mf]  = (uint32_t)((r & 7) << 4);                                       \
    }                                                                              \
    const int bRowL = ((lane >> 4) << 3) + (lane & 7);                             \
    const int bCoff = (lane >> 3) & 1;                                             \
    uint32_t bOff[2], bXr[2];                                                      \
    _Pragma("unroll")                                                              \
    for (int p = 0; p < 2; p++) {                                                  \
        const int r = warpN * 32 + p * 16 + bRowL;                                 \
        bOff[p] = (uint32_t)r * 128;                                               \
        bXr[p]  = (uint32_t)((r & 7) << 4);                                        \
    }                                                                              \
    _Pragma("unroll")                                                              \
    for (int mf = 0; mf < 4; mf++)                                                 \
        _Pragma("unroll")                                                          \
        for (int nf = 0; nf < 4; nf++)                                             \
            _Pragma("unroll")                                                      \
            for (int rr = 0; rr < 4; rr++) acc[mf][nf][rr] = 0.f;                  \
    const int Kc = K / BKH;                                                        \
    PREFETCH(0, 0);                                                                \
    asm volatile("cp.async.commit_group;");                                        \
    if (Kc > 1) PREFETCH(1, 1);                                                    \
    asm volatile("cp.async.commit_group;");                                        \
    for (int t = 0; t < Kc; t++) {                                                 \
        asm volatile("cp.async.wait_group 1;");                                    \
        __syncthreads();                                                           \
        if (t + 2 < Kc) PREFETCH(t + 2, (t + 2) % STAGES);                         \
        asm volatile("cp.async.commit_group;");                                    \
        const uint32_t sa = smem_base + (t % STAGES) * STAGE_WORDS * 4;            \
        const uint32_t sb = sa + A_TILE_WORDS * 4;                                 \
        _Pragma("unroll")                                                          \
        for (int ks = 0; ks < 4; ks++) {                                           \
            uint32_t af[4][4], bf[4][2];                                           \
            const uint32_t ac = (uint32_t)((2 * ks + aCoff) << 4);                 \
            const uint32_t bc = (uint32_t)((2 * ks + bCoff) << 4);                 \
            _Pragma("unroll")                                                      \
            for (int mf = 0; mf < 4; mf++)                                         \
                ldsm4(af[mf][0], af[mf][1], af[mf][2], af[mf][3],                  \
                      sa + aOff[mf] + (ac ^ aXr[mf]));                             \
            _Pragma("unroll")                                                      \
            for (int p = 0; p < 2; p++)                                            \
                ldsm4(bf[2 * p][0], bf[2 * p][1], bf[2 * p + 1][0], bf[2 * p + 1][1], \
                      sb + bOff[p] + (bc ^ bXr[p]));                               \
            _Pragma("unroll")                                                      \
            for (int mf = 0; mf < 4; mf++)                                         \
                _Pragma("unroll")                                                  \
                for (int nf = 0; nf < 4; nf++)                                     \
                    mma_f16(acc[mf][nf][0], acc[mf][nf][1], acc[mf][nf][2], acc[mf][nf][3], \
                            af[mf][0], af[mf][1], af[mf][2], af[mf][3],            \
                            bf[nf][0], bf[nf][1]);                                 \
        }                                                                          \
        __syncthreads();                                                           \
    }

#define PREFETCH(T, SLOT) do {                                                     \
        const uint32_t _sa = smem_base + (SLOT) * STAGE_WORDS * 4;                 \
        const uint32_t _sb = _sa + A_TILE_WORDS * 4;                               \
        const int _k0 = (T) * BKH;                                                 \
        _Pragma("unroll")                                                          \
        for (int i = 0; i < 4; i++) {                                              \
            const int r = lr + i * 32;                                             \
            cp16(_sa + swzw(r, lc * 4) * 4, Ag + (size_t)i * 32 * K + _k0);        \
        }                                                                          \
        _Pragma("unroll")                                                          \
        for (int i = 0; i < 4; i++) {                                              \
            const int r = lr + i * 32;                                             \
            const int gr = nbase + r;                                              \
            const int vld = gr < Nb;                                               \
            const __half* bp = B + (size_t)(vld ? gr : 0) * K + _k0 + lc * 8;      \
            cp16z(_sb + swzw(r, lc * 4) * 4, bp, vld);                             \
        }                                                                          \
    } while (0)

// =============== generic fp16 mma GEMM: C = scale*(A @ B^T) + bias ===============
// grid = (ceil(Ncols/BN), M/BM), block = 256 (8 warps: 2(M) x 4(N), 64x32 warp tiles)
__global__ void __launch_bounds__(256, 2)
gemm_h(const __half* __restrict__ A, const __half* __restrict__ B,
       const float* __restrict__ bias, void* __restrict__ Cv,
       int out_half, float scale, int Ncols, int Nb, int K, int ldc)
{
    extern __shared__ uint32_t sm32[];
    const int tid  = threadIdx.x;
    const int wid  = tid >> 5;
    const int lane = tid & 31;
    const int gid  = lane >> 2;
    const int tig  = lane & 3;
    const int warpM = wid & 1;
    const int warpN = wid >> 1;
    const int mbase = blockIdx.y * BM;
    const int nbase = blockIdx.x * BN;

    float acc[4][4][4];
    GEMM_MAINLOOP()

    float* Cf = (float*)Cv;
    __half* Ch = (__half*)Cv;
    #pragma unroll
    for (int mf = 0; mf < 4; mf++) {
        const int r0 = mbase + warpM * 64 + mf * 16 + gid;
        #pragma unroll
        for (int nf = 0; nf < 4; nf++) {
            const int col = nbase + warpN * 32 + nf * 8 + tig * 2;
            float v0 = acc[mf][nf][0] * scale;
            float v1 = acc[mf][nf][1] * scale;
            float v2 = acc[mf][nf][2] * scale;
            float v3 = acc[mf][nf][3] * scale;
            if (bias) {
                const float bz0 = (col < Ncols) ? __ldg(bias + col) : 0.f;
                const float bz1 = (col + 1 < Ncols) ? __ldg(bias + col + 1) : 0.f;
                v0 += bz0; v1 += bz1; v2 += bz0; v3 += bz1;
            }
            if (out_half) {
                if (col + 1 < Ncols) {
                    *(__half2*)(Ch + (size_t)r0 * ldc + col)       = __floats2half2_rn(v0, v1);
                    *(__half2*)(Ch + (size_t)(r0 + 8) * ldc + col) = __floats2half2_rn(v2, v3);
                } else if (col < Ncols) {
                    Ch[(size_t)r0 * ldc + col]       = __float2half_rn(v0);
                    Ch[(size_t)(r0 + 8) * ldc + col] = __float2half_rn(v2);
                }
            } else {
                if (col + 1 < Ncols) {
                    *(float2*)(Cf + (size_t)r0 * ldc + col)       = make_float2(v0, v1);
                    *(float2*)(Cf + (size_t)(r0 + 8) * ldc + col) = make_float2(v2, v3);
                } else if (col < Ncols) {
                    Cf[(size_t)r0 * ldc + col]       = v0;
                    Cf[(size_t)(r0 + 8) * ldc + col] = v2;
                }
            }
        }
    }
}

// =============== fused 4-way projection GEMM (R10 proven) ===============
// B = concat(Wq^T|Wk^T|Wv^T|Ws^T) [4096 x 1024]; each CTA's BN=128 cols in one segment.
// segment 0 -> qh (fp16), 1 -> kh (fp16), 2 -> v (fp32), 3 -> xr (fp32). All ldc = DIM.
__global__ void __launch_bounds__(256, 2)
gemm_proj4(const __half* __restrict__ A, const __half* __restrict__ B,
           const float* __restrict__ bq, const float* __restrict__ bk,
           const float* __restrict__ bv, const float* __restrict__ bs,
           __half* __restrict__ oq, __half* __restrict__ ok,
           float* __restrict__ ov, float* __restrict__ oxr,
           int Nb, int K)
{
    extern __shared__ uint32_t sm32[];
    const int tid  = threadIdx.x;
    const int wid  = tid >> 5;
    const int lane = tid & 31;
    const int gid  = lane >> 2;
    const int tig  = lane & 3;
    const int warpM = wid & 1;
    const int warpN = wid >> 1;
    const int mbase = blockIdx.y * BM;
    const int nbase = blockIdx.x * BN;

    float acc[4][4][4];
    GEMM_MAINLOOP()

    const int seg = nbase >> 10;                 // 0..3
    const float* bias = (seg == 0) ? bq : (seg == 1) ? bk : (seg == 2) ? bv : bs;
    const int oh = (seg < 2);
    __half* Ch = (seg == 0) ? oq : ok;
    float*  Cf = (seg == 2) ? ov : oxr;

    #pragma unroll
    for (int mf = 0; mf < 4; mf++) {
        const int r0 = mbase + warpM * 64 + mf * 16 + gid;
        #pragma unroll
        for (int nf = 0; nf < 4; nf++) {
            const int col = nbase + warpN * 32 + nf * 8 + tig * 2;
            const int cl = col & (DIM - 1);      // column within segment
            const float bz0 = __ldg(bias + cl);
            const float bz1 = __ldg(bias + cl + 1);
            const float v0 = acc[mf][nf][0] + bz0;
            const float v1 = acc[mf][nf][1] + bz1;
            const float v2 = acc[mf][nf][2] + bz0;
            const float v3 = acc[mf][nf][3] + bz1;
            if (oh) {
                *(__half2*)(Ch + (size_t)r0 * DIM + cl)       = __floats2half2_rn(v0, v1);
                *(__half2*)(Ch + (size_t)(r0 + 8) * DIM + cl) = __floats2half2_rn(v2, v3);
            } else {
                *(float2*)(Cf + (size_t)r0 * DIM + cl)       = make_float2(v0, v1);
                *(float2*)(Cf + (size_t)(r0 + 8) * DIM + cl) = make_float2(v2, v3);
            }
        }
    }
}

// =============== x -> fp16 copy ===============
__global__ void __launch_bounds__(256)
half_copy(const float* __restrict__ in, __half* __restrict__ out, int n8)
{
    int i = blockIdx.x * 256 + threadIdx.x;
    if (i < n8) {
        float4 f0 = ((const float4*)in)[2 * i];
        float4 f1 = ((const float4*)in)[2 * i + 1];
        __half2 h0 = __floats2half2_rn(f0.x, f0.y);
        __half2 h1 = __floats2half2_rn(f0.z, f0.w);
        __half2 h2 = __floats2half2_rn(f1.x, f1.y);
        __half2 h3 = __floats2half2_rn(f1.z, f1.w);
        uint4 o;
        o.x = *(uint32_t*)&h0; o.y = *(uint32_t*)&h1;
        o.z = *(uint32_t*)&h2; o.w = *(uint32_t*)&h3;
        ((uint4*)out)[i] = o;
    }
}

// =============== batched transpose of 4 DIM x DIM weights -> fp16 concat ===============
// blockIdx.z selects the source matrix; out offset = z * DIM*DIM.
__global__ void __launch_bounds__(256)
transpose4_h(const float* __restrict__ w0, const float* __restrict__ w1,
             const float* __restrict__ w2, const float* __restrict__ w3,
             __half* __restrict__ out)
{
    const float* srcs[4] = {w0, w1, w2, w3};
    const float* in = srcs[blockIdx.z];
    __half* o = out + (size_t)blockIdx.z * DIM * DIM;

    __shared__ float t[32][33];
    const int bx = blockIdx.x * 32, by = blockIdx.y * 32;
    const int txx = threadIdx.x, tyy = threadIdx.y;
    #pragma unroll
    for (int i = tyy; i < 32; i += 8)
        t[i][txx] = in[(size_t)(by + i) * DIM + bx + txx];
    __syncthreads();
    #pragma unroll
    for (int i = tyy; i < 32; i += 8)
        o[(size_t)(bx + i) * DIM + by + txx] = __float2half_rn(t[txx][i]);
}

// =============== generic transpose fp32 -> fp16: out[C,R] = half(in[R,C]^T) ===============
__global__ void __launch_bounds__(256)
transpose_h(const float* __restrict__ in, __half* __restrict__ out, int R, int C)
{
    __shared__ float t[32][33];
    const int bx = blockIdx.x * 32, by = blockIdx.y * 32;
    const int txx = threadIdx.x, tyy = threadIdx.y;
    #pragma unroll
    for (int i = tyy; i < 32; i += 8) {
        int y = by + i, x = bx + txx;
        if (y < R && x < C) t[i][txx] = in[(size_t)y * C + x];
    }
    __syncthreads();
    #pragma unroll
    for (int i = tyy; i < 32; i += 8) {
        int oy = bx + i, ox = by + txx;
        if (oy < C && ox < R) out[(size_t)oy * R + ox] = __float2half_rn(t[txx][i]);
    }
}

// =============== single-pass row softmax over 8192 fp16 cols (16B vectorized) ===============
__global__ void __launch_bounds__(256)
softmax_h(__half* __restrict__ S)
{
    const int row = blockIdx.x;
    uint4* p = (uint4*)(S + (size_t)row * N_ROWS);   // 1024 uint4 per row
    const int tid = threadIdx.x;

    uint4 raw[4];
    float2 v[16];
    float mx = -CUDART_INF_F;
    #pragma unroll
    for (int i = 0; i < 4; i++) {
        raw[i] = p[tid + i * 256];
        const __half2* h = (const __half2*)&raw[i];
        #pragma unroll
        for (int j = 0; j < 4; j++) {
            v[i * 4 + j] = __half22float2(h[j]);
            mx = fmaxf(mx, fmaxf(v[i * 4 + j].x, v[i * 4 + j].y));
        }
    }
    __shared__ float red[8];
    #pragma unroll
    for (int o = 16; o > 0; o >>= 1) mx = fmaxf(mx, __shfl_xor_sync(0xffffffffu, mx, o));
    if ((tid & 31) == 0) red[tid >> 5] = mx;
    __syncthreads();
    if (tid < 8) {
        float m = red[tid];
        #pragma unroll
        for (int o = 4; o > 0; o >>= 1) m = fmaxf(m, __shfl_xor_sync(0xffu, m, o));
        if (tid == 0) red[0] = m;
    }
    __syncthreads();
    mx = red[0];
    __syncthreads();

    float sum = 0.f;
    #pragma unroll
    for (int i = 0; i < 16; i++) {
        v[i].x = __expf(v[i].x - mx);
        v[i].y = __expf(v[i].y - mx);
        sum += v[i].x + v[i].y;
    }
    #pragma unroll
    for (int o = 16; o > 0; o >>= 1) sum += __shfl_xor_sync(0xffffffffu, sum, o);
    if ((tid & 31) == 0) red[tid >> 5] = sum;
    __syncthreads();
    if (tid < 8) {
        float s = red[tid];
        #pragma unroll
        for (int o = 4; o > 0; o >>= 1) s += __shfl_xor_sync(0xffu, s, o);
        if (tid == 0) red[0] = s;
    }
    __syncthreads();
    const float inv = 1.f / red[0];
    #pragma unroll
    for (int i = 0; i < 4; i++) {
        __half2* h = (__half2*)&raw[i];
        #pragma unroll
        for (int j = 0; j < 4; j++)
            h[j] = __floats2half2_rn(v[i * 4 + j].x * inv, v[i * 4 + j].y * inv);
        p[tid + i * 256] = raw[i];
    }
}

// =============== beta gate + mix -> fp16 m, one block per row ===============
__global__ void __launch_bounds__(256)
beta_mix(const float* __restrict__ a, const float* __restrict__ xr,
         const float* __restrict__ Wb, const float* __restrict__ bb,
         __half* __restrict__ Mout)
{
    const int row = blockIdx.x;
    const int tid = threadIdx.x;
    const float* ap = a  + (size_t)row * DIM;
    const float* xp = xr + (size_t)row * DIM;

    float partial = 0.f;
    #pragma unroll
    for (int i = tid; i < DIM; i += 256) {
        float av = ap[i], xv = xp[i];
        partial += av * Wb[i] + xv * Wb[DIM + i] + (av - xv) * Wb[2 * DIM + i];
    }
    __shared__ float red[8];
    #pragma unroll
    for (int o = 16; o > 0; o >>= 1) partial += __shfl_xor_sync(0xffffffffu, partial, o);
    if ((tid & 31) == 0) red[tid >> 5] = partial;
    __syncthreads();
    __shared__ float s_beta;
    if (tid == 0) {
        float t = 0.f;
        #pragma unroll
        for (int w = 0; w < 8; w++) t += red[w];
        t += bb[0];
        s_beta = 1.f / (1.f + expf(-t));
    }
    __syncthreads();
    const float beta = s_beta;
    __half* mp = Mout + (size_t)row * DIM;
    #pragma unroll
    for (int i = tid; i < DIM; i += 256)
        mp[i] = __float2half_rn(beta * xp[i] + (1.f - beta) * ap[i]);
}

// =============== launch ===============
extern "C" void kernel_launch(void* const* d_in, const int* in_sizes, int n_in,
                              void* d_out, int out_size)
{
    const float* x      = (const float*)d_in[0];
    const float* W_skip = (const float*)d_in[1];
    const float* b_skip = (const float*)d_in[2];
    const float* W_q    = (const float*)d_in[3];
    const float* b_q    = (const float*)d_in[4];
    const float* W_k    = (const float*)d_in[5];
    const float* b_k    = (const float*)d_in[6];
    const float* W_v    = (const float*)d_in[7];
    const float* b_v    = (const float*)d_in[8];
    const float* W_beta = (const float*)d_in[9];
    const float* b_beta = (const float*)d_in[10];
    const float* W_fc   = (const float*)d_in[11];
    const float* b_fc   = (const float*)d_in[12];
    float* out = (float*)d_out;

    __half *xh, *qh, *kh, *mh, *vTh, *Sh, *WcatT, *WfcT;
    float *v, *xr, *a;
    cudaGetSymbolAddress((void**)&xh,  g_xh);
    cudaGetSymbolAddress((void**)&qh,  g_qh);
    cudaGetSymbolAddress((void**)&kh,  g_kh);
    cudaGetSymbolAddress((void**)&v,   g_v);
    cudaGetSymbolAddress((void**)&xr,  g_xr);
    cudaGetSymbolAddress((void**)&a,   g_a);
    cudaGetSymbolAddress((void**)&mh,  g_mh);
    cudaGetSymbolAddress((void**)&vTh, g_vTh);
    cudaGetSymbolAddress((void**)&Sh,  g_Sh);
    cudaGetSymbolAddress((void**)&WcatT, g_WcatT);
    cudaGetSymbolAddress((void**)&WfcT,  g_WfcT);

    cudaFuncSetAttribute(gemm_h,     cudaFuncAttributeMaxDynamicSharedMemorySize, DYN_SMEM);
    cudaFuncSetAttribute(gemm_proj4, cudaFuncAttributeMaxDynamicSharedMemorySize, DYN_SMEM);

    const dim3 tb(32, 8);
    const dim3 blk(256);
    const dim3 gProj4(4 * DIM / BN, N_ROWS / BM);       // (32, 64)
    const dim3 gAv(DIM / BN, N_ROWS / BM);              // (8, 64)
    const dim3 gScore(N_ROWS / BN, N_ROWS / BM);        // (64, 64)
    const dim3 gFc((NCLS + BN - 1) / BN, N_ROWS / BM);  // (8, 64)

    // launch order: ncu (-s 5 -c 1) captures the scores GEMM now (index 5)
    half_copy<<<(N_ROWS * DIM / 8 + 255) / 256, 256>>>(x, xh, N_ROWS * DIM / 8);      // 0
    transpose4_h<<<dim3(32, 32, 4), tb>>>(W_q, W_k, W_v, W_skip, WcatT);              // 1
    transpose_h<<<dim3((NCLS + 31) / 32, 32), tb>>>(W_fc, WfcT, DIM, NCLS);           // 2
    gemm_proj4<<<gProj4, blk, DYN_SMEM>>>(xh, WcatT, b_q, b_k, b_v, b_skip,
                                          qh, kh, v, xr, 4 * DIM, DIM);               // 3
    transpose_h<<<dim3(DIM / 32, N_ROWS / 32), tb>>>(v, vTh, N_ROWS, DIM);            // 4
    gemm_h<<<gScore, blk, DYN_SMEM>>>(qh, kh, nullptr, Sh, 1, 1.f / 32.f,
                                      N_ROWS, N_ROWS, DIM, N_ROWS);                   // 5 <- ncu

    softmax_h<<<N_ROWS, 256>>>(Sh);

    gemm_h<<<gAv, blk, DYN_SMEM>>>(Sh, vTh, nullptr, a, 0, 1.f, DIM, DIM, N_ROWS, DIM);

    beta_mix<<<N_ROWS, 256>>>(a, xr, W_beta, b_beta, mh);

    gemm_h<<<gFc, blk, DYN_SMEM>>>(mh, WfcT, b_fc, out, 0, 1.f, NCLS, NCLS, DIM, NCLS);
}

// round 14
// speedup vs baseline: 1.1110x; 1.0138x over previous
#include <cuda_runtime.h>
#include <cuda_fp16.h>
#include <math_constants.h>
#include <cstdint>

#define N_ROWS 8192
#define DIM    1024
#define NCLS   1000

// ---- fp16 mma.sync GEMM tile config (R10/R13 proven config) ----
#define BM 128
#define BN 128
#define BKH 64                                  // halves per K-chunk (128B row)
#define STAGES 3
#define A_TILE_WORDS (BM * BKH / 2)             // 4096 32-bit words (16KB)
#define STAGE_WORDS  (2 * A_TILE_WORDS)         // 8192 words (32KB)
#define DYN_SMEM     (STAGES * STAGE_WORDS * 4) // 96KB -> 2 CTAs/SM

// ---------------- scratch (device globals: allocation-free) ----------------
__device__ __half g_xh [N_ROWS * DIM];
__device__ __half g_qh [N_ROWS * DIM];
__device__ __half g_kh [N_ROWS * DIM];
__device__ float  g_v  [N_ROWS * DIM];
__device__ float  g_xr [N_ROWS * DIM];
__device__ float  g_a  [N_ROWS * DIM];
__device__ __half g_mh [N_ROWS * DIM];
__device__ __half g_vTh[DIM * N_ROWS];
__device__ __half g_Sh [(size_t)N_ROWS * N_ROWS];   // 128 MB fp16 scores
__device__ __half g_WcatT[4 * DIM * DIM];           // concat(Wq^T|Wk^T|Wv^T|Ws^T)
__device__ __half g_WfcT [NCLS * DIM];

// ================= helpers =================
__device__ __forceinline__ uint32_t smem_u32(const void* p) {
    uint32_t a;
    asm("{ .reg .u64 t; cvta.to.shared.u64 t, %1; cvt.u32.u64 %0, t; }" : "=r"(a) : "l"(p));
    return a;
}
// word-granular XOR swizzle (16B-chunk granularity): (row r, word w) -> word offset
__device__ __forceinline__ int swzw(int r, int w) {
    return r * 32 + (w ^ ((r & 7) << 2));
}
__device__ __forceinline__ void cp16(uint32_t saddr, const void* g) {
    asm volatile("cp.async.cg.shared.global [%0], [%1], 16;" :: "r"(saddr), "l"(g));
}
__device__ __forceinline__ void cp16z(uint32_t saddr, const void* g, int valid) {
    int sz = valid ? 16 : 0;
    asm volatile("cp.async.cg.shared.global [%0], [%1], 16, %2;" :: "r"(saddr), "l"(g), "r"(sz));
}
__device__ __forceinline__ void ldsm4(uint32_t& r0, uint32_t& r1, uint32_t& r2, uint32_t& r3,
                                      uint32_t addr) {
    asm volatile("ldmatrix.sync.aligned.m8n8.x4.shared.b16 {%0,%1,%2,%3}, [%4];"
                 : "=r"(r0), "=r"(r1), "=r"(r2), "=r"(r3) : "r"(addr));
}
__device__ __forceinline__ void mma_f16(float& d0, float& d1, float& d2, float& d3,
                                        uint32_t a0, uint32_t a1, uint32_t a2, uint32_t a3,
                                        uint32_t b0, uint32_t b1) {
    asm volatile(
        "mma.sync.aligned.m16n8k16.row.col.f32.f16.f16.f32 "
        "{%0,%1,%2,%3}, {%4,%5,%6,%7}, {%8,%9}, {%0,%1,%2,%3};"
        : "+f"(d0), "+f"(d1), "+f"(d2), "+f"(d3)
        : "r"(a0), "r"(a1), "r"(a2), "r"(a3), "r"(b0), "r"(b1));
}

// ---- shared mainloop body (acc layout: [4][4][4], 64x32 warp tile) ----
// ONE barrier per chunk: with 3-deep stage rotation, the top __syncthreads of
// iteration t orders all warps past iteration t-1's reads of slot (t-1)%3
// before PREFETCH(t+2) overwrites that same slot. The old bottom barrier was
// redundant and is removed.
#define GEMM_MAINLOOP()                                                            \
    const int lr = tid >> 3;                                                       \
    const int lc = tid & 7;                                                        \
    const __half* Ag = A + (size_t)(mbase + lr) * K + lc * 8;                      \
    const uint32_t smem_base = smem_u32(sm32);                                     \
    const int aRowL = lane & 15;                                                   \
    const int aCoff = lane >> 4;                                                   \
    uint32_t aOff[4], aXr[4];                                                      \
    _Pragma("unroll")                                                              \
    for (int mf = 0; mf < 4; mf++) {                                               \
        const int r = warpM * 64 + mf * 16 + aRowL;                                \
        aOff[mf] = (uint32_t)r * 128;                                              \
        aXr[mf]  = (uint32_t)((r & 7) << 4);                                       \
    }                                                                              \
    const int bRowL = ((lane >> 4) << 3) + (lane & 7);                             \
    const int bCoff = (lane >> 3) & 1;                                             \
    uint32_t bOff[2], bXr[2];                                                      \
    _Pragma("unroll")                                                              \
    for (int p = 0; p < 2; p++) {                                                  \
        const int r = warpN * 32 + p * 16 + bRowL;                                 \
        bOff[p] = (uint32_t)r * 128;                                               \
        bXr[p]  = (uint32_t)((r & 7) << 4);                                        \
    }                                                                              \
    _Pragma("unroll")                                                              \
    for (int mf = 0; mf < 4; mf++)                                                 \
        _Pragma("unroll")                                                          \
        for (int nf = 0; nf < 4; nf++)                                             \
            _Pragma("unroll")                                                      \
            for (int rr = 0; rr < 4; rr++) acc[mf][nf][rr] = 0.f;                  \
    const int Kc = K / BKH;                                                        \
    PREFETCH(0, 0);                                                                \
    asm volatile("cp.async.commit_group;");                                        \
    if (Kc > 1) PREFETCH(1, 1);                                                    \
    asm volatile("cp.async.commit_group;");                                        \
    for (int t = 0; t < Kc; t++) {                                                 \
        asm volatile("cp.async.wait_group 1;");                                    \
        __syncthreads();                                                           \
        if (t + 2 < Kc) PREFETCH(t + 2, (t + 2) % STAGES);                         \
        asm volatile("cp.async.commit_group;");                                    \
        const uint32_t sa = smem_base + (t % STAGES) * STAGE_WORDS * 4;            \
        const uint32_t sb = sa + A_TILE_WORDS * 4;                                 \
        _Pragma("unroll")                                                          \
        for (int ks = 0; ks < 4; ks++) {                                           \
            uint32_t af[4][4], bf[4][2];                                           \
            const uint32_t ac = (uint32_t)((2 * ks + aCoff) << 4);                 \
            const uint32_t bc = (uint32_t)((2 * ks + bCoff) << 4);                 \
            _Pragma("unroll")                                                      \
            for (int mf = 0; mf < 4; mf++)                                         \
                ldsm4(af[mf][0], af[mf][1], af[mf][2], af[mf][3],                  \
                      sa + aOff[mf] + (ac ^ aXr[mf]));                             \
            _Pragma("unroll")                                                      \
            for (int p = 0; p < 2; p++)                                            \
                ldsm4(bf[2 * p][0], bf[2 * p][1], bf[2 * p + 1][0], bf[2 * p + 1][1], \
                      sb + bOff[p] + (bc ^ bXr[p]));                               \
            _Pragma("unroll")                                                      \
            for (int mf = 0; mf < 4; mf++)                                         \
                _Pragma("unroll")                                                  \
                for (int nf = 0; nf < 4; nf++)                                     \
                    mma_f16(acc[mf][nf][0], acc[mf][nf][1], acc[mf][nf][2], acc[mf][nf][3], \
                            af[mf][0], af[mf][1], af[mf][2], af[mf][3],            \
                            bf[nf][0], bf[nf][1]);                                 \
        }                                                                          \
    }

#define PREFETCH(T, SLOT) do {                                                     \
        const uint32_t _sa = smem_base + (SLOT) * STAGE_WORDS * 4;                 \
        const uint32_t _sb = _sa + A_TILE_WORDS * 4;                               \
        const int _k0 = (T) * BKH;                                                 \
        _Pragma("unroll")                                                          \
        for (int i = 0; i < 4; i++) {                                              \
            const int r = lr + i * 32;                                             \
            cp16(_sa + swzw(r, lc * 4) * 4, Ag + (size_t)i * 32 * K + _k0);        \
        }                                                                          \
        _Pragma("unroll")                                                          \
        for (int i = 0; i < 4; i++) {                                              \
            const int r = lr + i * 32;                                             \
            const int gr = nbase + r;                                              \
            const int vld = gr < Nb;                                               \
            const __half* bp = B + (size_t)(vld ? gr : 0) * K + _k0 + lc * 8;      \
            cp16z(_sb + swzw(r, lc * 4) * 4, bp, vld);                             \
        }                                                                          \
    } while (0)

// =============== generic fp16 mma GEMM: C = scale*(A @ B^T) + bias ===============
// grid = (ceil(Ncols/BN), M/BM), block = 256 (8 warps: 2(M) x 4(N), 64x32 warp tiles)
__global__ void __launch_bounds__(256, 2)
gemm_h(const __half* __restrict__ A, const __half* __restrict__ B,
       const float* __restrict__ bias, void* __restrict__ Cv,
       int out_half, float scale, int Ncols, int Nb, int K, int ldc)
{
    extern __shared__ uint32_t sm32[];
    const int tid  = threadIdx.x;
    const int wid  = tid >> 5;
    const int lane = tid & 31;
    const int gid  = lane >> 2;
    const int tig  = lane & 3;
    const int warpM = wid & 1;
    const int warpN = wid >> 1;
    const int mbase = blockIdx.y * BM;
    const int nbase = blockIdx.x * BN;

    float acc[4][4][4];
    GEMM_MAINLOOP()

    float* Cf = (float*)Cv;
    __half* Ch = (__half*)Cv;
    #pragma unroll
    for (int mf = 0; mf < 4; mf++) {
        const int r0 = mbase + warpM * 64 + mf * 16 + gid;
        #pragma unroll
        for (int nf = 0; nf < 4; nf++) {
            const int col = nbase + warpN * 32 + nf * 8 + tig * 2;
            float v0 = acc[mf][nf][0] * scale;
            float v1 = acc[mf][nf][1] * scale;
            float v2 = acc[mf][nf][2] * scale;
            float v3 = acc[mf][nf][3] * scale;
            if (bias) {
                const float bz0 = (col < Ncols) ? __ldg(bias + col) : 0.f;
                const float bz1 = (col + 1 < Ncols) ? __ldg(bias + col + 1) : 0.f;
                v0 += bz0; v1 += bz1; v2 += bz0; v3 += bz1;
            }
            if (out_half) {
                if (col + 1 < Ncols) {
                    *(__half2*)(Ch + (size_t)r0 * ldc + col)       = __floats2half2_rn(v0, v1);
                    *(__half2*)(Ch + (size_t)(r0 + 8) * ldc + col) = __floats2half2_rn(v2, v3);
                } else if (col < Ncols) {
                    Ch[(size_t)r0 * ldc + col]       = __float2half_rn(v0);
                    Ch[(size_t)(r0 + 8) * ldc + col] = __float2half_rn(v2);
                }
            } else {
                if (col + 1 < Ncols) {
                    *(float2*)(Cf + (size_t)r0 * ldc + col)       = make_float2(v0, v1);
                    *(float2*)(Cf + (size_t)(r0 + 8) * ldc + col) = make_float2(v2, v3);
                } else if (col < Ncols) {
                    Cf[(size_t)r0 * ldc + col]       = v0;
                    Cf[(size_t)(r0 + 8) * ldc + col] = v2;
                }
            }
        }
    }
}

// =============== fused 4-way projection GEMM ===============
// B = concat(Wq^T|Wk^T|Wv^T|Ws^T) [4096 x 1024]; each CTA's BN=128 cols in one segment.
// segment 0 -> qh (fp16), 1 -> kh (fp16), 2 -> v (fp32), 3 -> xr (fp32). All ldc = DIM.
__global__ void __launch_bounds__(256, 2)
gemm_proj4(const __half* __restrict__ A, const __half* __restrict__ B,
           const float* __restrict__ bq, const float* __restrict__ bk,
           const float* __restrict__ bv, const float* __restrict__ bs,
           __half* __restrict__ oq, __half* __restrict__ ok,
           float* __restrict__ ov, float* __restrict__ oxr,
           int Nb, int K)
{
    extern __shared__ uint32_t sm32[];
    const int tid  = threadIdx.x;
    const int wid  = tid >> 5;
    const int lane = tid & 31;
    const int gid  = lane >> 2;
    const int tig  = lane & 3;
    const int warpM = wid & 1;
    const int warpN = wid >> 1;
    const int mbase = blockIdx.y * BM;
    const int nbase = blockIdx.x * BN;

    float acc[4][4][4];
    GEMM_MAINLOOP()

    const int seg = nbase >> 10;                 // 0..3
    const float* bias = (seg == 0) ? bq : (seg == 1) ? bk : (seg == 2) ? bv : bs;
    const int oh = (seg < 2);
    __half* Ch = (seg == 0) ? oq : ok;
    float*  Cf = (seg == 2) ? ov : oxr;

    #pragma unroll
    for (int mf = 0; mf < 4; mf++) {
        const int r0 = mbase + warpM * 64 + mf * 16 + gid;
        #pragma unroll
        for (int nf = 0; nf < 4; nf++) {
            const int col = nbase + warpN * 32 + nf * 8 + tig * 2;
            const int cl = col & (DIM - 1);      // column within segment
            const float bz0 = __ldg(bias + cl);
            const float bz1 = __ldg(bias + cl + 1);
            const float v0 = acc[mf][nf][0] + bz0;
            const float v1 = acc[mf][nf][1] + bz1;
            const float v2 = acc[mf][nf][2] + bz0;
            const float v3 = acc[mf][nf][3] + bz1;
            if (oh) {
                *(__half2*)(Ch + (size_t)r0 * DIM + cl)       = __floats2half2_rn(v0, v1);
                *(__half2*)(Ch + (size_t)(r0 + 8) * DIM + cl) = __floats2half2_rn(v2, v3);
            } else {
                *(float2*)(Cf + (size_t)r0 * DIM + cl)       = make_float2(v0, v1);
                *(float2*)(Cf + (size_t)(r0 + 8) * DIM + cl) = make_float2(v2, v3);
            }
        }
    }
}

// =============== x -> fp16 copy ===============
__global__ void __launch_bounds__(256)
half_copy(const float* __restrict__ in, __half* __restrict__ out, int n8)
{
    int i = blockIdx.x * 256 + threadIdx.x;
    if (i < n8) {
        float4 f0 = ((const float4*)in)[2 * i];
        float4 f1 = ((const float4*)in)[2 * i + 1];
        __half2 h0 = __floats2half2_rn(f0.x, f0.y);
        __half2 h1 = __floats2half2_rn(f0.z, f0.w);
        __half2 h2 = __floats2half2_rn(f1.x, f1.y);
        __half2 h3 = __floats2half2_rn(f1.z, f1.w);
        uint4 o;
        o.x = *(uint32_t*)&h0; o.y = *(uint32_t*)&h1;
        o.z = *(uint32_t*)&h2; o.w = *(uint32_t*)&h3;
        ((uint4*)out)[i] = o;
    }
}

// =============== batched transpose of 4 DIM x DIM weights -> fp16 concat ===============
__global__ void __launch_bounds__(256)
transpose4_h(const float* __restrict__ w0, const float* __restrict__ w1,
             const float* __restrict__ w2, const float* __restrict__ w3,
             __half* __restrict__ out)
{
    const float* srcs[4] = {w0, w1, w2, w3};
    const float* in = srcs[blockIdx.z];
    __half* o = out + (size_t)blockIdx.z * DIM * DIM;

    __shared__ float t[32][33];
    const int bx = blockIdx.x * 32, by = blockIdx.y * 32;
    const int txx = threadIdx.x, tyy = threadIdx.y;
    #pragma unroll
    for (int i = tyy; i < 32; i += 8)
        t[i][txx] = in[(size_t)(by + i) * DIM + bx + txx];
    __syncthreads();
    #pragma unroll
    for (int i = tyy; i < 32; i += 8)
        o[(size_t)(bx + i) * DIM + by + txx] = __float2half_rn(t[txx][i]);
}

// =============== generic transpose fp32 -> fp16: out[C,R] = half(in[R,C]^T) ===============
__global__ void __launch_bounds__(256)
transpose_h(const float* __restrict__ in, __half* __restrict__ out, int R, int C)
{
    __shared__ float t[32][33];
    const int bx = blockIdx.x * 32, by = blockIdx.y * 32;
    const int txx = threadIdx.x, tyy = threadIdx.y;
    #pragma unroll
    for (int i = tyy; i < 32; i += 8) {
        int y = by + i, x = bx + txx;
        if (y < R && x < C) t[i][txx] = in[(size_t)y * C + x];
    }
    __syncthreads();
    #pragma unroll
    for (int i = tyy; i < 32; i += 8) {
        int oy = bx + i, ox = by + txx;
        if (oy < C && ox < R) out[(size_t)oy * R + ox] = __float2half_rn(t[txx][i]);
    }
}

// =============== single-pass row softmax over 8192 fp16 cols (16B vectorized) ===============
__global__ void __launch_bounds__(256)
softmax_h(__half* __restrict__ S)
{
    const int row = blockIdx.x;
    uint4* p = (uint4*)(S + (size_t)row * N_ROWS);   // 1024 uint4 per row
    const int tid = threadIdx.x;

    uint4 raw[4];
    float2 v[16];
    float mx = -CUDART_INF_F;
    #pragma unroll
    for (int i = 0; i < 4; i++) {
        raw[i] = p[tid + i * 256];
        const __half2* h = (const __half2*)&raw[i];
        #pragma unroll
        for (int j = 0; j < 4; j++) {
            v[i * 4 + j] = __half22float2(h[j]);
            mx = fmaxf(mx, fmaxf(v[i * 4 + j].x, v[i * 4 + j].y));
        }
    }
    __shared__ float red[8];
    #pragma unroll
    for (int o = 16; o > 0; o >>= 1) mx = fmaxf(mx, __shfl_xor_sync(0xffffffffu, mx, o));
    if ((tid & 31) == 0) red[tid >> 5] = mx;
    __syncthreads();
    if (tid < 8) {
        float m = red[tid];
        #pragma unroll
        for (int o = 4; o > 0; o >>= 1) m = fmaxf(m, __shfl_xor_sync(0xffu, m, o));
        if (tid == 0) red[0] = m;
    }
    __syncthreads();
    mx = red[0];
    __syncthreads();

    float sum = 0.f;
    #pragma unroll
    for (int i = 0; i < 16; i++) {
        v[i].x = __expf(v[i].x - mx);
        v[i].y = __expf(v[i].y - mx);
        sum += v[i].x + v[i].y;
    }
    #pragma unroll
    for (int o = 16; o > 0; o >>= 1) sum += __shfl_xor_sync(0xffffffffu, sum, o);
    if ((tid & 31) == 0) red[tid >> 5] = sum;
    __syncthreads();
    if (tid < 8) {
        float s = red[tid];
        #pragma unroll
        for (int o = 4; o > 0; o >>= 1) s += __shfl_xor_sync(0xffu, s, o);
        if (tid == 0) red[0] = s;
    }
    __syncthreads();
    const float inv = 1.f / red[0];
    #pragma unroll
    for (int i = 0; i < 4; i++) {
        __half2* h = (__half2*)&raw[i];
        #pragma unroll
        for (int j = 0; j < 4; j++)
            h[j] = __floats2half2_rn(v[i * 4 + j].x * inv, v[i * 4 + j].y * inv);
        p[tid + i * 256] = raw[i];
    }
}

// =============== beta gate + mix -> fp16 m, one block per row ===============
__global__ void __launch_bounds__(256)
beta_mix(const float* __restrict__ a, const float* __restrict__ xr,
         const float* __restrict__ Wb, const float* __restrict__ bb,
         __half* __restrict__ Mout)
{
    const int row = blockIdx.x;
    const int tid = threadIdx.x;
    const float* ap = a  + (size_t)row * DIM;
    const float* xp = xr + (size_t)row * DIM;

    float partial = 0.f;
    #pragma unroll
    for (int i = tid; i < DIM; i += 256) {
        float av = ap[i], xv = xp[i];
        partial += av * Wb[i] + xv * Wb[DIM + i] + (av - xv) * Wb[2 * DIM + i];
    }
    __shared__ float red[8];
    #pragma unroll
    for (int o = 16; o > 0; o >>= 1) partial += __shfl_xor_sync(0xffffffffu, partial, o);
    if ((tid & 31) == 0) red[tid >> 5] = partial;
    __syncthreads();
    __shared__ float s_beta;
    if (tid == 0) {
        float t = 0.f;
        #pragma unroll
        for (int w = 0; w < 8; w++) t += red[w];
        t += bb[0];
        s_beta = 1.f / (1.f + expf(-t));
    }
    __syncthreads();
    const float beta = s_beta;
    __half* mp = Mout + (size_t)row * DIM;
    #pragma unroll
    for (int i = tid; i < DIM; i += 256)
        mp[i] = __float2half_rn(beta * xp[i] + (1.f - beta) * ap[i]);
}

// =============== launch ===============
extern "C" void kernel_launch(void* const* d_in, const int* in_sizes, int n_in,
                              void* d_out, int out_size)
{
    const float* x      = (const float*)d_in[0];
    const float* W_skip = (const float*)d_in[1];
    const float* b_skip = (const float*)d_in[2];
    const float* W_q    = (const float*)d_in[3];
    const float* b_q    = (const float*)d_in[4];
    const float* W_k    = (const float*)d_in[5];
    const float* b_k    = (const float*)d_in[6];
    const float* W_v    = (const float*)d_in[7];
    const float* b_v    = (const float*)d_in[8];
    const float* W_beta = (const float*)d_in[9];
    const float* b_beta = (const float*)d_in[10];
    const float* W_fc   = (const float*)d_in[11];
    const float* b_fc   = (const float*)d_in[12];
    float* out = (float*)d_out;

    __half *xh, *qh, *kh, *mh, *vTh, *Sh, *WcatT, *WfcT;
    float *v, *xr, *a;
    cudaGetSymbolAddress((void**)&xh,  g_xh);
    cudaGetSymbolAddress((void**)&qh,  g_qh);
    cudaGetSymbolAddress((void**)&kh,  g_kh);
    cudaGetSymbolAddress((void**)&v,   g_v);
    cudaGetSymbolAddress((void**)&xr,  g_xr);
    cudaGetSymbolAddress((void**)&a,   g_a);
    cudaGetSymbolAddress((void**)&mh,  g_mh);
    cudaGetSymbolAddress((void**)&vTh, g_vTh);
    cudaGetSymbolAddress((void**)&Sh,  g_Sh);
    cudaGetSymbolAddress((void**)&WcatT, g_WcatT);
    cudaGetSymbolAddress((void**)&WfcT,  g_WfcT);

    cudaFuncSetAttribute(gemm_h,     cudaFuncAttributeMaxDynamicSharedMemorySize, DYN_SMEM);
    cudaFuncSetAttribute(gemm_proj4, cudaFuncAttributeMaxDynamicSharedMemorySize, DYN_SMEM);

    const dim3 tb(32, 8);
    const dim3 blk(256);
    const dim3 gProj4(4 * DIM / BN, N_ROWS / BM);       // (32, 64)
    const dim3 gAv(DIM / BN, N_ROWS / BM);              // (8, 64)
    const dim3 gScore(N_ROWS / BN, N_ROWS / BM);        // (64, 64)
    const dim3 gFc((NCLS + BN - 1) / BN, N_ROWS / BM);  // (8, 64)

    // launch order: ncu (-s 5 -c 1) captures the scores GEMM (index 5)
    half_copy<<<(N_ROWS * DIM / 8 + 255) / 256, 256>>>(x, xh, N_ROWS * DIM / 8);      // 0
    transpose4_h<<<dim3(32, 32, 4), tb>>>(W_q, W_k, W_v, W_skip, WcatT);              // 1
    transpose_h<<<dim3((NCLS + 31) / 32, 32), tb>>>(W_fc, WfcT, DIM, NCLS);           // 2
    gemm_proj4<<<gProj4, blk, DYN_SMEM>>>(xh, WcatT, b_q, b_k, b_v, b_skip,
                                          qh, kh, v, xr, 4 * DIM, DIM);               // 3
    transpose_h<<<dim3(DIM / 32, N_ROWS / 32), tb>>>(v, vTh, N_ROWS, DIM);            // 4
    gemm_h<<<gScore, blk, DYN_SMEM>>>(qh, kh, nullptr, Sh, 1, 1.f / 32.f,
                                      N_ROWS, N_ROWS, DIM, N_ROWS);                   // 5 <- ncu

    softmax_h<<<N_ROWS, 256>>>(Sh);

    gemm_h<<<gAv, blk, DYN_SMEM>>>(Sh, vTh, nullptr, a, 0, 1.f, DIM, DIM, N_ROWS, DIM);

    beta_mix<<<N_ROWS, 256>>>(a, xr, W_beta, b_beta, mh);

    gemm_h<<<gFc, blk, DYN_SMEM>>>(mh, WfcT, b_fc, out, 0, 1.f, NCLS, NCLS, DIM, NCLS);
}

// round 15
// speedup vs baseline: 1.1382x; 1.0245x over previous
#include <cuda_runtime.h>
#include <cuda_fp16.h>
#include <math_constants.h>
#include <cstdint>

#define N_ROWS 8192
#define DIM    1024
#define NCLS   1000

// ---- fp16 mma.sync GEMM tile config (proven) ----
#define BM 128
#define BN 128
#define BKH 64
#define STAGES 3
#define A_TILE_WORDS (BM * BKH / 2)
#define STAGE_WORDS  (2 * A_TILE_WORDS)
#define DYN_SMEM     (STAGES * STAGE_WORDS * 4) // 96KB -> 2 CTAs/SM

// ---------------- scratch ----------------
__device__ __half g_xh [N_ROWS * DIM];
__device__ __half g_qh [N_ROWS * DIM];
__device__ __half g_kh [N_ROWS * DIM];
__device__ __half g_vh [N_ROWS * DIM];
__device__ float  g_xr [N_ROWS * DIM];
__device__ float  g_a  [N_ROWS * DIM];
__device__ __half g_mh [N_ROWS * DIM];
__device__ __half g_vTh[DIM * N_ROWS];
__device__ __half g_Sh [(size_t)N_ROWS * N_ROWS];   // exp(scores) fp16
__device__ float  g_part[64 * N_ROWS];              // per-colblock partial rowsums
__device__ float  g_rowsum[N_ROWS];
__device__ __half g_WcatT[4 * DIM * DIM];
__device__ __half g_WfcT [NCLS * DIM];

// ================= helpers =================
__device__ __forceinline__ uint32_t smem_u32(const void* p) {
    uint32_t a;
    asm("{ .reg .u64 t; cvta.to.shared.u64 t, %1; cvt.u32.u64 %0, t; }" : "=r"(a) : "l"(p));
    return a;
}
__device__ __forceinline__ int swzw(int r, int w) {
    return r * 32 + (w ^ ((r & 7) << 2));
}
__device__ __forceinline__ void cp16(uint32_t saddr, const void* g) {
    asm volatile("cp.async.cg.shared.global [%0], [%1], 16;" :: "r"(saddr), "l"(g));
}
__device__ __forceinline__ void cp16z(uint32_t saddr, const void* g, int valid) {
    int sz = valid ? 16 : 0;
    asm volatile("cp.async.cg.shared.global [%0], [%1], 16, %2;" :: "r"(saddr), "l"(g), "r"(sz));
}
__device__ __forceinline__ void ldsm4(uint32_t& r0, uint32_t& r1, uint32_t& r2, uint32_t& r3,
                                      uint32_t addr) {
    asm volatile("ldmatrix.sync.aligned.m8n8.x4.shared.b16 {%0,%1,%2,%3}, [%4];"
                 : "=r"(r0), "=r"(r1), "=r"(r2), "=r"(r3) : "r"(addr));
}
__device__ __forceinline__ void mma_f16(float& d0, float& d1, float& d2, float& d3,
                                        uint32_t a0, uint32_t a1, uint32_t a2, uint32_t a3,
                                        uint32_t b0, uint32_t b1) {
    asm volatile(
        "mma.sync.aligned.m16n8k16.row.col.f32.f16.f16.f32 "
        "{%0,%1,%2,%3}, {%4,%5,%6,%7}, {%8,%9}, {%0,%1,%2,%3};"
        : "+f"(d0), "+f"(d1), "+f"(d2), "+f"(d3)
        : "r"(a0), "r"(a1), "r"(a2), "r"(a3), "r"(b0), "r"(b1));
}

// ---- shared mainloop (single barrier per chunk; 3-deep stage rotation) ----
#define GEMM_MAINLOOP()                                                            \
    const int lr = tid >> 3;                                                       \
    const int lc = tid & 7;                                                        \
    const __half* Ag = A + (size_t)(mbase + lr) * K + lc * 8;                      \
    const uint32_t smem_base = smem_u32(sm32);                                     \
    const int aRowL = lane & 15;                                                   \
    const int aCoff = lane >> 4;                                                   \
    uint32_t aOff[4], aXr[4];                                                      \
    _Pragma("unroll")                                                              \
    for (int mf = 0; mf < 4; mf++) {                                               \
        const int r = warpM * 64 + mf * 16 + aRowL;                                \
        aOff[mf] = (uint32_t)r * 128;                                              \
        aXr[mf]  = (uint32_t)((r & 7) << 4);                                       \
    }                                                                              \
    const int bRowL = ((lane >> 4) << 3) + (lane & 7);                             \
    const int bCoff = (lane >> 3) & 1;                                             \
    uint32_t bOff[2], bXr[2];                                                      \
    _Pragma("unroll")                                                              \
    for (int p = 0; p < 2; p++) {                                                  \
        const int r = warpN * 32 + p * 16 + bRowL;                                 \
        bOff[p] = (uint32_t)r * 128;                                               \
        bXr[p]  = (uint32_t)((r & 7) << 4);                                        \
    }                                                                              \
    _Pragma("unroll")                                                              \
    for (int mf = 0; mf < 4; mf++)                                                 \
        _Pragma("unroll")                                                          \
        for (int nf = 0; nf < 4; nf++)                                             \
            _Pragma("unroll")                                                      \
            for (int rr = 0; rr < 4; rr++) acc[mf][nf][rr] = 0.f;                  \
    const int Kc = K / BKH;                                                        \
    PREFETCH(0, 0);                                                                \
    asm volatile("cp.async.commit_group;");                                        \
    if (Kc > 1) PREFETCH(1, 1);                                                    \
    asm volatile("cp.async.commit_group;");                                        \
    for (int t = 0; t < Kc; t++) {                                                 \
        asm volatile("cp.async.wait_group 1;");                                    \
        __syncthreads();                                                           \
        if (t + 2 < Kc) PREFETCH(t + 2, (t + 2) % STAGES);                         \
        asm volatile("cp.async.commit_group;");                                    \
        const uint32_t sa = smem_base + (t % STAGES) * STAGE_WORDS * 4;            \
        const uint32_t sb = sa + A_TILE_WORDS * 4;                                 \
        _Pragma("unroll")                                                          \
        for (int ks = 0; ks < 4; ks++) {                                           \
            uint32_t af[4][4], bf[4][2];                                           \
            const uint32_t ac = (uint32_t)((2 * ks + aCoff) << 4);                 \
            const uint32_t bc = (uint32_t)((2 * ks + bCoff) << 4);                 \
            _Pragma("unroll")                                                      \
            for (int mf = 0; mf < 4; mf++)                                         \
                ldsm4(af[mf][0], af[mf][1], af[mf][2], af[mf][3],                  \
                      sa + aOff[mf] + (ac ^ aXr[mf]));                             \
            _Pragma("unroll")                                                      \
            for (int p = 0; p < 2; p++)                                            \
                ldsm4(bf[2 * p][0], bf[2 * p][1], bf[2 * p + 1][0], bf[2 * p + 1][1], \
                      sb + bOff[p] + (bc ^ bXr[p]));                               \
            _Pragma("unroll")                                                      \
            for (int mf = 0; mf < 4; mf++)                                         \
                _Pragma("unroll")                                                  \
                for (int nf = 0; nf < 4; nf++)                                     \
                    mma_f16(acc[mf][nf][0], acc[mf][nf][1], acc[mf][nf][2], acc[mf][nf][3], \
                            af[mf][0], af[mf][1], af[mf][2], af[mf][3],            \
                            bf[nf][0], bf[nf][1]);                                 \
        }                                                                          \
    }

#define PREFETCH(T, SLOT) do {                                                     \
        const uint32_t _sa = smem_base + (SLOT) * STAGE_WORDS * 4;                 \
        const uint32_t _sb = _sa + A_TILE_WORDS * 4;                               \
        const int _k0 = (T) * BKH;                                                 \
        _Pragma("unroll")                                                          \
        for (int i = 0; i < 4; i++) {                                              \
            const int r = lr + i * 32;                                             \
            cp16(_sa + swzw(r, lc * 4) * 4, Ag + (size_t)i * 32 * K + _k0);        \
        }                                                                          \
        _Pragma("unroll")                                                          \
        for (int i = 0; i < 4; i++) {                                              \
            const int r = lr + i * 32;                                             \
            const int gr = nbase + r;                                              \
            const int vld = gr < Nb;                                               \
            const __half* bp = B + (size_t)(vld ? gr : 0) * K + _k0 + lc * 8;      \
            cp16z(_sb + swzw(r, lc * 4) * 4, bp, vld);                             \
        }                                                                          \
    } while (0)

// =============== generic fp16 mma GEMM ===============
// mode 0: C = scale*(A@B^T) + bias  (fp32 or fp16 out per out_half)
// mode 1: C(fp16) = exp(scale*(A@B^T)); partial rowsums -> aux[blockIdx.x*8192 + row]
// mode 2: C(fp32) = (A@B^T) / aux[row]   (aux = rowsum)
__global__ void __launch_bounds__(256, 2)
gemm_h(const __half* __restrict__ A, const __half* __restrict__ B,
       const float* __restrict__ bias, void* __restrict__ Cv,
       int out_half, float scale, int Ncols, int Nb, int K, int ldc,
       int mode, float* __restrict__ aux)
{
    extern __shared__ uint32_t sm32[];
    const int tid  = threadIdx.x;
    const int wid  = tid >> 5;
    const int lane = tid & 31;
    const int gid  = lane >> 2;
    const int tig  = lane & 3;
    const int warpM = wid & 1;
    const int warpN = wid >> 1;
    const int mbase = blockIdx.y * BM;
    const int nbase = blockIdx.x * BN;

    float acc[4][4][4];
    GEMM_MAINLOOP()

    if (mode == 1) {
        // exp + per-CTA partial rowsum (deterministic reduction)
        __syncthreads();                       // stage buffers dead; reuse smem
        float* psum = (float*)sm32;            // [4 warpN][128 rows]
        __half* Ch = (__half*)Cv;
        #pragma unroll
        for (int mf = 0; mf < 4; mf++) {
            const int lrow = warpM * 64 + mf * 16 + gid;   // 0..127
            const int r0 = mbase + lrow;
            float s0 = 0.f, s1 = 0.f;
            #pragma unroll
            for (int nf = 0; nf < 4; nf++) {
                const int col = nbase + warpN * 32 + nf * 8 + tig * 2;
                const float e0 = __expf(acc[mf][nf][0] * scale);
                const float e1 = __expf(acc[mf][nf][1] * scale);
                const float e2 = __expf(acc[mf][nf][2] * scale);
                const float e3 = __expf(acc[mf][nf][3] * scale);
                s0 += e0 + e1;
                s1 += e2 + e3;
                *(__half2*)(Ch + (size_t)r0 * ldc + col)       = __floats2half2_rn(e0, e1);
                *(__half2*)(Ch + (size_t)(r0 + 8) * ldc + col) = __floats2half2_rn(e2, e3);
            }
            s0 += __shfl_xor_sync(0xffffffffu, s0, 1);
            s0 += __shfl_xor_sync(0xffffffffu, s0, 2);
            s1 += __shfl_xor_sync(0xffffffffu, s1, 1);
            s1 += __shfl_xor_sync(0xffffffffu, s1, 2);
            if (tig == 0) {
                psum[warpN * 128 + lrow]     = s0;
                psum[warpN * 128 + lrow + 8] = s1;
            }
        }
        __syncthreads();
        if (tid < 128) {
            const float t = psum[tid] + psum[128 + tid] + psum[256 + tid] + psum[384 + tid];
            aux[(size_t)blockIdx.x * N_ROWS + mbase + tid] = t;
        }
        return;
    }

    float* Cf = (float*)Cv;
    __half* Ch = (__half*)Cv;
    #pragma unroll
    for (int mf = 0; mf < 4; mf++) {
        const int r0 = mbase + warpM * 64 + mf * 16 + gid;
        float inv0 = 1.f, inv1 = 1.f;
        if (mode == 2) {
            inv0 = 1.f / aux[r0];
            inv1 = 1.f / aux[r0 + 8];
        }
        #pragma unroll
        for (int nf = 0; nf < 4; nf++) {
            const int col = nbase + warpN * 32 + nf * 8 + tig * 2;
            float v0 = acc[mf][nf][0] * scale;
            float v1 = acc[mf][nf][1] * scale;
            float v2 = acc[mf][nf][2] * scale;
            float v3 = acc[mf][nf][3] * scale;
            if (mode == 2) { v0 *= inv0; v1 *= inv0; v2 *= inv1; v3 *= inv1; }
            if (bias) {
                const float bz0 = (col < Ncols) ? __ldg(bias + col) : 0.f;
                const float bz1 = (col + 1 < Ncols) ? __ldg(bias + col + 1) : 0.f;
                v0 += bz0; v1 += bz1; v2 += bz0; v3 += bz1;
            }
            if (out_half) {
                if (col + 1 < Ncols) {
                    *(__half2*)(Ch + (size_t)r0 * ldc + col)       = __floats2half2_rn(v0, v1);
                    *(__half2*)(Ch + (size_t)(r0 + 8) * ldc + col) = __floats2half2_rn(v2, v3);
                } else if (col < Ncols) {
                    Ch[(size_t)r0 * ldc + col]       = __float2half_rn(v0);
                    Ch[(size_t)(r0 + 8) * ldc + col] = __float2half_rn(v2);
                }
            } else {
                if (col + 1 < Ncols) {
                    *(float2*)(Cf + (size_t)r0 * ldc + col)       = make_float2(v0, v1);
                    *(float2*)(Cf + (size_t)(r0 + 8) * ldc + col) = make_float2(v2, v3);
                } else if (col < Ncols) {
                    Cf[(size_t)r0 * ldc + col]       = v0;
                    Cf[(size_t)(r0 + 8) * ldc + col] = v2;
                }
            }
        }
    }
}

// =============== fused 4-way projection GEMM ===============
// seg 0 -> qh fp16, 1 -> kh fp16, 2 -> vh fp16 (row-major), 3 -> xr fp32.
__global__ void __launch_bounds__(256, 2)
gemm_proj4(const __half* __restrict__ A, const __half* __restrict__ B,
           const float* __restrict__ bq, const float* __restrict__ bk,
           const float* __restrict__ bv, const float* __restrict__ bs,
           __half* __restrict__ oq, __half* __restrict__ ok,
           __half* __restrict__ ov, float* __restrict__ oxr,
           int Nb, int K)
{
    extern __shared__ uint32_t sm32[];
    const int tid  = threadIdx.x;
    const int wid  = tid >> 5;
    const int lane = tid & 31;
    const int gid  = lane >> 2;
    const int tig  = lane & 3;
    const int warpM = wid & 1;
    const int warpN = wid >> 1;
    const int mbase = blockIdx.y * BM;
    const int nbase = blockIdx.x * BN;

    float acc[4][4][4];
    GEMM_MAINLOOP()

    const int seg = nbase >> 10;
    const float* bias = (seg == 0) ? bq : (seg == 1) ? bk : (seg == 2) ? bv : bs;
    const int oh = (seg < 3);
    __half* Ch = (seg == 0) ? oq : (seg == 1) ? ok : ov;

    #pragma unroll
    for (int mf = 0; mf < 4; mf++) {
        const int r0 = mbase + warpM * 64 + mf * 16 + gid;
        #pragma unroll
        for (int nf = 0; nf < 4; nf++) {
            const int col = nbase + warpN * 32 + nf * 8 + tig * 2;
            const int cl = col & (DIM - 1);
            const float bz0 = __ldg(bias + cl);
            const float bz1 = __ldg(bias + cl + 1);
            const float v0 = acc[mf][nf][0] + bz0;
            const float v1 = acc[mf][nf][1] + bz1;
            const float v2 = acc[mf][nf][2] + bz0;
            const float v3 = acc[mf][nf][3] + bz1;
            if (oh) {
                *(__half2*)(Ch + (size_t)r0 * DIM + cl)       = __floats2half2_rn(v0, v1);
                *(__half2*)(Ch + (size_t)(r0 + 8) * DIM + cl) = __floats2half2_rn(v2, v3);
            } else {
                *(float2*)(oxr + (size_t)r0 * DIM + cl)       = make_float2(v0, v1);
                *(float2*)(oxr + (size_t)(r0 + 8) * DIM + cl) = make_float2(v2, v3);
            }
        }
    }
}

// =============== x -> fp16 copy ===============
__global__ void __launch_bounds__(256)
half_copy(const float* __restrict__ in, __half* __restrict__ out, int n8)
{
    int i = blockIdx.x * 256 + threadIdx.x;
    if (i < n8) {
        float4 f0 = ((const float4*)in)[2 * i];
        float4 f1 = ((const float4*)in)[2 * i + 1];
        __half2 h0 = __floats2half2_rn(f0.x, f0.y);
        __half2 h1 = __floats2half2_rn(f0.z, f0.w);
        __half2 h2 = __floats2half2_rn(f1.x, f1.y);
        __half2 h3 = __floats2half2_rn(f1.z, f1.w);
        uint4 o;
        o.x = *(uint32_t*)&h0; o.y = *(uint32_t*)&h1;
        o.z = *(uint32_t*)&h2; o.w = *(uint32_t*)&h3;
        ((uint4*)out)[i] = o;
    }
}

// =============== batched transpose of 4 DIM x DIM weights -> fp16 concat ===============
__global__ void __launch_bounds__(256)
transpose4_h(const float* __restrict__ w0, const float* __restrict__ w1,
             const float* __restrict__ w2, const float* __restrict__ w3,
             __half* __restrict__ out)
{
    const float* srcs[4] = {w0, w1, w2, w3};
    const float* in = srcs[blockIdx.z];
    __half* o = out + (size_t)blockIdx.z * DIM * DIM;

    __shared__ float t[32][33];
    const int bx = blockIdx.x * 32, by = blockIdx.y * 32;
    const int txx = threadIdx.x, tyy = threadIdx.y;
    #pragma unroll
    for (int i = tyy; i < 32; i += 8)
        t[i][txx] = in[(size_t)(by + i) * DIM + bx + txx];
    __syncthreads();
    #pragma unroll
    for (int i = tyy; i < 32; i += 8)
        o[(size_t)(bx + i) * DIM + by + txx] = __float2half_rn(t[txx][i]);
}

// =============== generic transpose fp32 -> fp16 ===============
__global__ void __launch_bounds__(256)
transpose_h(const float* __restrict__ in, __half* __restrict__ out, int R, int C)
{
    __shared__ float t[32][33];
    const int bx = blockIdx.x * 32, by = blockIdx.y * 32;
    const int txx = threadIdx.x, tyy = threadIdx.y;
    #pragma unroll
    for (int i = tyy; i < 32; i += 8) {
        int y = by + i, x = bx + txx;
        if (y < R && x < C) t[i][txx] = in[(size_t)y * C + x];
    }
    __syncthreads();
    #pragma unroll
    for (int i = tyy; i < 32; i += 8) {
        int oy = bx + i, ox = by + txx;
        if (oy < C && ox < R) out[(size_t)oy * R + ox] = __float2half_rn(t[txx][i]);
    }
}

// =============== fp16 -> fp16 transpose (exact pass-through) ===============
__global__ void __launch_bounds__(256)
transpose_hh(const __half* __restrict__ in, __half* __restrict__ out, int R, int C)
{
    __shared__ float t[32][33];
    const int bx = blockIdx.x * 32, by = blockIdx.y * 32;
    const int txx = threadIdx.x, tyy = threadIdx.y;
    #pragma unroll
    for (int i = tyy; i < 32; i += 8)
        t[i][txx] = __half2float(in[(size_t)(by + i) * C + bx + txx]);
    __syncthreads();
    #pragma unroll
    for (int i = tyy; i < 32; i += 8)
        out[(size_t)(bx + i) * R + by + txx] = __float2half_rn(t[txx][i]);
}

// =============== rowsum reduction: rowsum[r] = sum_b part[b][r] ===============
__global__ void __launch_bounds__(256)
reduce_rowsum(const float* __restrict__ part, float* __restrict__ rowsum)
{
    const int r = blockIdx.x * 256 + threadIdx.x;
    float s = 0.f;
    #pragma unroll
    for (int b = 0; b < 64; b++) s += part[(size_t)b * N_ROWS + r];
    rowsum[r] = s;
}

// =============== beta gate + mix -> fp16 m, one block per row ===============
__global__ void __launch_bounds__(256)
beta_mix(const float* __restrict__ a, const float* __restrict__ xr,
         const float* __restrict__ Wb, const float* __restrict__ bb,
         __half* __restrict__ Mout)
{
    const int row = blockIdx.x;
    const int tid = threadIdx.x;
    const float* ap = a  + (size_t)row * DIM;
    const float* xp = xr + (size_t)row * DIM;

    float partial = 0.f;
    #pragma unroll
    for (int i = tid; i < DIM; i += 256) {
        float av = ap[i], xv = xp[i];
        partial += av * Wb[i] + xv * Wb[DIM + i] + (av - xv) * Wb[2 * DIM + i];
    }
    __shared__ float red[8];
    #pragma unroll
    for (int o = 16; o > 0; o >>= 1) partial += __shfl_xor_sync(0xffffffffu, partial, o);
    if ((tid & 31) == 0) red[tid >> 5] = partial;
    __syncthreads();
    __shared__ float s_beta;
    if (tid == 0) {
        float t = 0.f;
        #pragma unroll
        for (int w = 0; w < 8; w++) t += red[w];
        t += bb[0];
        s_beta = 1.f / (1.f + expf(-t));
    }
    __syncthreads();
    const float beta = s_beta;
    __half* mp = Mout + (size_t)row * DIM;
    #pragma unroll
    for (int i = tid; i < DIM; i += 256)
        mp[i] = __float2half_rn(beta * xp[i] + (1.f - beta) * ap[i]);
}

// =============== launch ===============
extern "C" void kernel_launch(void* const* d_in, const int* in_sizes, int n_in,
                              void* d_out, int out_size)
{
    const float* x      = (const float*)d_in[0];
    const float* W_skip = (const float*)d_in[1];
    const float* b_skip = (const float*)d_in[2];
    const float* W_q    = (const float*)d_in[3];
    const float* b_q    = (const float*)d_in[4];
    const float* W_k    = (const float*)d_in[5];
    const float* b_k    = (const float*)d_in[6];
    const float* W_v    = (const float*)d_in[7];
    const float* b_v    = (const float*)d_in[8];
    const float* W_beta = (const float*)d_in[9];
    const float* b_beta = (const float*)d_in[10];
    const float* W_fc   = (const float*)d_in[11];
    const float* b_fc   = (const float*)d_in[12];
    float* out = (float*)d_out;

    __half *xh, *qh, *kh, *vh, *mh, *vTh, *Sh, *WcatT, *WfcT;
    float *xr, *a, *part, *rowsum;
    cudaGetSymbolAddress((void**)&xh,  g_xh);
    cudaGetSymbolAddress((void**)&qh,  g_qh);
    cudaGetSymbolAddress((void**)&kh,  g_kh);
    cudaGetSymbolAddress((void**)&vh,  g_vh);
    cudaGetSymbolAddress((void**)&xr,  g_xr);
    cudaGetSymbolAddress((void**)&a,   g_a);
    cudaGetSymbolAddress((void**)&mh,  g_mh);
    cudaGetSymbolAddress((void**)&vTh, g_vTh);
    cudaGetSymbolAddress((void**)&Sh,  g_Sh);
    cudaGetSymbolAddress((void**)&part,   g_part);
    cudaGetSymbolAddress((void**)&rowsum, g_rowsum);
    cudaGetSymbolAddress((void**)&WcatT, g_WcatT);
    cudaGetSymbolAddress((void**)&WfcT,  g_WfcT);

    cudaFuncSetAttribute(gemm_h,     cudaFuncAttributeMaxDynamicSharedMemorySize, DYN_SMEM);
    cudaFuncSetAttribute(gemm_proj4, cudaFuncAttributeMaxDynamicSharedMemorySize, DYN_SMEM);

    const dim3 tb(32, 8);
    const dim3 blk(256);
    const dim3 gProj4(4 * DIM / BN, N_ROWS / BM);       // (32, 64)
    const dim3 gAv(DIM / BN, N_ROWS / BM);              // (8, 64)
    const dim3 gScore(N_ROWS / BN, N_ROWS / BM);        // (64, 64)
    const dim3 gFc((NCLS + BN - 1) / BN, N_ROWS / BM);  // (8, 64)

    // ncu (-s 5 -c 1) captures the scores GEMM (index 5)
    half_copy<<<(N_ROWS * DIM / 8 + 255) / 256, 256>>>(x, xh, N_ROWS * DIM / 8);      // 0
    transpose4_h<<<dim3(32, 32, 4), tb>>>(W_q, W_k, W_v, W_skip, WcatT);              // 1
    transpose_h<<<dim3((NCLS + 31) / 32, 32), tb>>>(W_fc, WfcT, DIM, NCLS);           // 2
    gemm_proj4<<<gProj4, blk, DYN_SMEM>>>(xh, WcatT, b_q, b_k, b_v, b_skip,
                                          qh, kh, vh, xr, 4 * DIM, DIM);              // 3
    transpose_hh<<<dim3(DIM / 32, N_ROWS / 32), tb>>>(vh, vTh, N_ROWS, DIM);          // 4
    // scores: S = exp((q@k^T)/32), partial rowsums -> part
    gemm_h<<<gScore, blk, DYN_SMEM>>>(qh, kh, nullptr, Sh, 1, 1.f / 32.f,
                                      N_ROWS, N_ROWS, DIM, N_ROWS, 1, part);          // 5 <- ncu

    reduce_rowsum<<<N_ROWS / 256, 256>>>(part, rowsum);

    // attn@v with rowsum division fused
    gemm_h<<<gAv, blk, DYN_SMEM>>>(Sh, vTh, nullptr, a, 0, 1.f,
                                   DIM, DIM, N_ROWS, DIM, 2, rowsum);

    beta_mix<<<N_ROWS, 256>>>(a, xr, W_beta, b_beta, mh);

    gemm_h<<<gFc, blk, DYN_SMEM>>>(mh, WfcT, b_fc, out, 0, 1.f,
                                   NCLS, NCLS, DIM, NCLS, 0, nullptr);
}

// round 16
// speedup vs baseline: 1.1545x; 1.0143x over previous
#include <cuda_runtime.h>
#include <cuda_fp16.h>
#include <math_constants.h>
#include <cstdint>

#define N_ROWS 8192
#define DIM    1024
#define NCLS   1000

// ---- fp16 mma.sync GEMM tile config (proven) ----
#define BM 128
#define BN 128
#define BKH 64
#define STAGES 3
#define A_TILE_WORDS (BM * BKH / 2)
#define STAGE_WORDS  (2 * A_TILE_WORDS)
#define DYN_SMEM     (STAGES * STAGE_WORDS * 4) // 96KB -> 2 CTAs/SM

// ---------------- scratch ----------------
__device__ __half g_xh [N_ROWS * DIM];
__device__ __half g_qh [N_ROWS * DIM];
__device__ __half g_kh [N_ROWS * DIM];
__device__ float  g_xr [N_ROWS * DIM];
__device__ float  g_a  [N_ROWS * DIM];
__device__ __half g_mh [N_ROWS * DIM];
__device__ __half g_vTh[DIM * N_ROWS];
__device__ __half g_Sh [(size_t)N_ROWS * N_ROWS];   // exp(scores) fp16
__device__ float  g_part[64 * N_ROWS];              // per-colblock partial rowsums
__device__ float  g_rowsum[N_ROWS];
__device__ __half g_WcatT[4 * DIM * DIM];
__device__ __half g_WfcT [NCLS * DIM];

// ================= helpers =================
__device__ __forceinline__ uint32_t smem_u32(const void* p) {
    uint32_t a;
    asm("{ .reg .u64 t; cvta.to.shared.u64 t, %1; cvt.u32.u64 %0, t; }" : "=r"(a) : "l"(p));
    return a;
}
__device__ __forceinline__ int swzw(int r, int w) {
    return r * 32 + (w ^ ((r & 7) << 2));
}
__device__ __forceinline__ void cp16(uint32_t saddr, const void* g) {
    asm volatile("cp.async.cg.shared.global [%0], [%1], 16;" :: "r"(saddr), "l"(g));
}
__device__ __forceinline__ void cp16z(uint32_t saddr, const void* g, int valid) {
    int sz = valid ? 16 : 0;
    asm volatile("cp.async.cg.shared.global [%0], [%1], 16, %2;" :: "r"(saddr), "l"(g), "r"(sz));
}
__device__ __forceinline__ void ldsm4(uint32_t& r0, uint32_t& r1, uint32_t& r2, uint32_t& r3,
                                      uint32_t addr) {
    asm volatile("ldmatrix.sync.aligned.m8n8.x4.shared.b16 {%0,%1,%2,%3}, [%4];"
                 : "=r"(r0), "=r"(r1), "=r"(r2), "=r"(r3) : "r"(addr));
}
__device__ __forceinline__ void mma_f16(float& d0, float& d1, float& d2, float& d3,
                                        uint32_t a0, uint32_t a1, uint32_t a2, uint32_t a3,
                                        uint32_t b0, uint32_t b1) {
    asm volatile(
        "mma.sync.aligned.m16n8k16.row.col.f32.f16.f16.f32 "
        "{%0,%1,%2,%3}, {%4,%5,%6,%7}, {%8,%9}, {%0,%1,%2,%3};"
        : "+f"(d0), "+f"(d1), "+f"(d2), "+f"(d3)
        : "r"(a0), "r"(a1), "r"(a2), "r"(a3), "r"(b0), "r"(b1));
}

// ---- shared mainloop (single barrier per chunk; 3-deep stage rotation) ----
#define GEMM_MAINLOOP()                                                            \
    const int lr = tid >> 3;                                                       \
    const int lc = tid & 7;                                                        \
    const __half* Ag = A + (size_t)(mbase + lr) * K + lc * 8;                      \
    const uint32_t smem_base = smem_u32(sm32);                                     \
    const int aRowL = lane & 15;                                                   \
    const int aCoff = lane >> 4;                                                   \
    uint32_t aOff[4], aXr[4];                                                      \
    _Pragma("unroll")                                                              \
    for (int mf = 0; mf < 4; mf++) {                                               \
        const int r = warpM * 64 + mf * 16 + aRowL;                                \
        aOff[mf] = (uint32_t)r * 128;                                              \
        aXr[mf]  = (uint32_t)((r & 7) << 4);                                       \
    }                                                                              \
    const int bRowL = ((lane >> 4) << 3) + (lane & 7);                             \
    const int bCoff = (lane >> 3) & 1;                                             \
    uint32_t bOff[2], bXr[2];                                                      \
    _Pragma("unroll")                                                              \
    for (int p = 0; p < 2; p++) {                                                  \
        const int r = warpN * 32 + p * 16 + bRowL;                                 \
        bOff[p] = (uint32_t)r * 128;                                               \
        bXr[p]  = (uint32_t)((r & 7) << 4);                                        \
    }                                                                              \
    _Pragma("unroll")                                                              \
    for (int mf = 0; mf < 4; mf++)                                                 \
        _Pragma("unroll")                                                          \
        for (int nf = 0; nf < 4; nf++)                                             \
            _Pragma("unroll")                                                      \
            for (int rr = 0; rr < 4; rr++) acc[mf][nf][rr] = 0.f;                  \
    const int Kc = K / BKH;                                                        \
    PREFETCH(0, 0);                                                                \
    asm volatile("cp.async.commit_group;");                                        \
    if (Kc > 1) PREFETCH(1, 1);                                                    \
    asm volatile("cp.async.commit_group;");                                        \
    for (int t = 0; t < Kc; t++) {                                                 \
        asm volatile("cp.async.wait_group 1;");                                    \
        __syncthreads();                                                           \
        if (t + 2 < Kc) PREFETCH(t + 2, (t + 2) % STAGES);                         \
        asm volatile("cp.async.commit_group;");                                    \
        const uint32_t sa = smem_base + (t % STAGES) * STAGE_WORDS * 4;            \
        const uint32_t sb = sa + A_TILE_WORDS * 4;                                 \
        _Pragma("unroll")                                                          \
        for (int ks = 0; ks < 4; ks++) {                                           \
            uint32_t af[4][4], bf[4][2];                                           \
            const uint32_t ac = (uint32_t)((2 * ks + aCoff) << 4);                 \
            const uint32_t bc = (uint32_t)((2 * ks + bCoff) << 4);                 \
            _Pragma("unroll")                                                      \
            for (int mf = 0; mf < 4; mf++)                                         \
                ldsm4(af[mf][0], af[mf][1], af[mf][2], af[mf][3],                  \
                      sa + aOff[mf] + (ac ^ aXr[mf]));                             \
            _Pragma("unroll")                                                      \
            for (int p = 0; p < 2; p++)                                            \
                ldsm4(bf[2 * p][0], bf[2 * p][1], bf[2 * p + 1][0], bf[2 * p + 1][1], \
                      sb + bOff[p] + (bc ^ bXr[p]));                               \
            _Pragma("unroll")                                                      \
            for (int mf = 0; mf < 4; mf++)                                         \
                _Pragma("unroll")                                                  \
                for (int nf = 0; nf < 4; nf++)                                     \
                    mma_f16(acc[mf][nf][0], acc[mf][nf][1], acc[mf][nf][2], acc[mf][nf][3], \
                            af[mf][0], af[mf][1], af[mf][2], af[mf][3],            \
                            bf[nf][0], bf[nf][1]);                                 \
        }                                                                          \
    }

#define PREFETCH(T, SLOT) do {                                                     \
        const uint32_t _sa = smem_base + (SLOT) * STAGE_WORDS * 4;                 \
        const uint32_t _sb = _sa + A_TILE_WORDS * 4;                               \
        const int _k0 = (T) * BKH;                                                 \
        _Pragma("unroll")                                                          \
        for (int i = 0; i < 4; i++) {                                              \
            const int r = lr + i * 32;                                             \
            cp16(_sa + swzw(r, lc * 4) * 4, Ag + (size_t)i * 32 * K + _k0);        \
        }                                                                          \
        _Pragma("unroll")                                                          \
        for (int i = 0; i < 4; i++) {                                              \
            const int r = lr + i * 32;                                             \
            const int gr = nbase + r;                                              \
            const int vld = gr < Nb;                                               \
            const __half* bp = B + (size_t)(vld ? gr : 0) * K + _k0 + lc * 8;      \
            cp16z(_sb + swzw(r, lc * 4) * 4, bp, vld);                             \
        }                                                                          \
    } while (0)

// =============== generic fp16 mma GEMM ===============
// mode 0: C = scale*(A@B^T) + bias
// mode 1: C(fp16) = exp(scale*(A@B^T)); partial rowsums -> aux[blockIdx.x*8192 + row]
// mode 2: C(fp32) = (A@B^T) / aux[row]
__global__ void __launch_bounds__(256, 2)
gemm_h(const __half* __restrict__ A, const __half* __restrict__ B,
       const float* __restrict__ bias, void* __restrict__ Cv,
       int out_half, float scale, int Ncols, int Nb, int K, int ldc,
       int mode, float* __restrict__ aux)
{
    extern __shared__ uint32_t sm32[];
    const int tid  = threadIdx.x;
    const int wid  = tid >> 5;
    const int lane = tid & 31;
    const int gid  = lane >> 2;
    const int tig  = lane & 3;
    const int warpM = wid & 1;
    const int warpN = wid >> 1;
    const int mbase = blockIdx.y * BM;
    const int nbase = blockIdx.x * BN;

    float acc[4][4][4];
    GEMM_MAINLOOP()

    if (mode == 1) {
        __syncthreads();
        float* psum = (float*)sm32;
        __half* Ch = (__half*)Cv;
        #pragma unroll
        for (int mf = 0; mf < 4; mf++) {
            const int lrow = warpM * 64 + mf * 16 + gid;
            const int r0 = mbase + lrow;
            float s0 = 0.f, s1 = 0.f;
            #pragma unroll
            for (int nf = 0; nf < 4; nf++) {
                const int col = nbase + warpN * 32 + nf * 8 + tig * 2;
                const float e0 = __expf(acc[mf][nf][0] * scale);
                const float e1 = __expf(acc[mf][nf][1] * scale);
                const float e2 = __expf(acc[mf][nf][2] * scale);
                const float e3 = __expf(acc[mf][nf][3] * scale);
                s0 += e0 + e1;
                s1 += e2 + e3;
                *(__half2*)(Ch + (size_t)r0 * ldc + col)       = __floats2half2_rn(e0, e1);
                *(__half2*)(Ch + (size_t)(r0 + 8) * ldc + col) = __floats2half2_rn(e2, e3);
            }
            s0 += __shfl_xor_sync(0xffffffffu, s0, 1);
            s0 += __shfl_xor_sync(0xffffffffu, s0, 2);
            s1 += __shfl_xor_sync(0xffffffffu, s1, 1);
            s1 += __shfl_xor_sync(0xffffffffu, s1, 2);
            if (tig == 0) {
                psum[warpN * 128 + lrow]     = s0;
                psum[warpN * 128 + lrow + 8] = s1;
            }
        }
        __syncthreads();
        if (tid < 128) {
            const float t = psum[tid] + psum[128 + tid] + psum[256 + tid] + psum[384 + tid];
            aux[(size_t)blockIdx.x * N_ROWS + mbase + tid] = t;
        }
        return;
    }

    float* Cf = (float*)Cv;
    __half* Ch = (__half*)Cv;
    #pragma unroll
    for (int mf = 0; mf < 4; mf++) {
        const int r0 = mbase + warpM * 64 + mf * 16 + gid;
        float inv0 = 1.f, inv1 = 1.f;
        if (mode == 2) {
            inv0 = 1.f / aux[r0];
            inv1 = 1.f / aux[r0 + 8];
        }
        #pragma unroll
        for (int nf = 0; nf < 4; nf++) {
            const int col = nbase + warpN * 32 + nf * 8 + tig * 2;
            float v0 = acc[mf][nf][0] * scale;
            float v1 = acc[mf][nf][1] * scale;
            float v2 = acc[mf][nf][2] * scale;
            float v3 = acc[mf][nf][3] * scale;
            if (mode == 2) { v0 *= inv0; v1 *= inv0; v2 *= inv1; v3 *= inv1; }
            if (bias) {
                const float bz0 = (col < Ncols) ? __ldg(bias + col) : 0.f;
                const float bz1 = (col + 1 < Ncols) ? __ldg(bias + col + 1) : 0.f;
                v0 += bz0; v1 += bz1; v2 += bz0; v3 += bz1;
            }
            if (out_half) {
                if (col + 1 < Ncols) {
                    *(__half2*)(Ch + (size_t)r0 * ldc + col)       = __floats2half2_rn(v0, v1);
                    *(__half2*)(Ch + (size_t)(r0 + 8) * ldc + col) = __floats2half2_rn(v2, v3);
                } else if (col < Ncols) {
                    Ch[(size_t)r0 * ldc + col]       = __float2half_rn(v0);
                    Ch[(size_t)(r0 + 8) * ldc + col] = __float2half_rn(v2);
                }
            } else {
                if (col + 1 < Ncols) {
                    *(float2*)(Cf + (size_t)r0 * ldc + col)       = make_float2(v0, v1);
                    *(float2*)(Cf + (size_t)(r0 + 8) * ldc + col) = make_float2(v2, v3);
                } else if (col < Ncols) {
                    Cf[(size_t)r0 * ldc + col]       = v0;
                    Cf[(size_t)(r0 + 8) * ldc + col] = v2;
                }
            }
        }
    }
}

// =============== fused 4-way projection GEMM ===============
// seg 0 -> qh fp16, 1 -> kh fp16, 2 -> vT fp16 via smem transpose, 3 -> xr fp32.
__global__ void __launch_bounds__(256, 2)
gemm_proj4(const __half* __restrict__ A, const __half* __restrict__ B,
           const float* __restrict__ bq, const float* __restrict__ bk,
           const float* __restrict__ bv, const float* __restrict__ bs,
           __half* __restrict__ oq, __half* __restrict__ ok,
           __half* __restrict__ ovT, float* __restrict__ oxr,
           int Nb, int K)
{
    extern __shared__ uint32_t sm32[];
    const int tid  = threadIdx.x;
    const int wid  = tid >> 5;
    const int lane = tid & 31;
    const int gid  = lane >> 2;
    const int tig  = lane & 3;
    const int warpM = wid & 1;
    const int warpN = wid >> 1;
    const int mbase = blockIdx.y * BM;
    const int nbase = blockIdx.x * BN;

    float acc[4][4][4];
    GEMM_MAINLOOP()

    const int seg = nbase >> 10;
    const float* bias = (seg == 0) ? bq : (seg == 1) ? bk : (seg == 2) ? bv : bs;

    if (seg == 2) {
        // v segment: smem-transpose the 128x128 tile, then coalesced vT writes.
        __syncthreads();                        // mainloop smem reads complete
        __half (*Tt)[136] = (__half(*)[136])sm32;   // 128 x 136 halves (16B-aligned rows)
        #pragma unroll
        for (int mf = 0; mf < 4; mf++) {
            const int lrow = warpM * 64 + mf * 16 + gid;
            #pragma unroll
            for (int nf = 0; nf < 4; nf++) {
                const int lc2 = warpN * 32 + nf * 8 + tig * 2;   // local col 0..127
                const int cl = (nbase & (DIM - 1)) + lc2;
                const float bz0 = __ldg(bias + cl);
                const float bz1 = __ldg(bias + cl + 1);
                Tt[lc2][lrow]         = __float2half_rn(acc[mf][nf][0] + bz0);
                Tt[lc2 + 1][lrow]     = __float2half_rn(acc[mf][nf][1] + bz1);
                Tt[lc2][lrow + 8]     = __float2half_rn(acc[mf][nf][2] + bz0);
                Tt[lc2 + 1][lrow + 8] = __float2half_rn(acc[mf][nf][3] + bz1);
            }
        }
        __syncthreads();
        const int segc = nbase & (DIM - 1);
        #pragma unroll
        for (int i = 0; i < 8; i++) {
            const int idx = tid + i * 256;      // 0..2047
            const int c = idx >> 4;             // 0..127
            const int r = (idx & 15) * 8;       // 0..120
            const uint4 val = *(const uint4*)&Tt[c][r];
            *(uint4*)(ovT + (size_t)(segc + c) * N_ROWS + mbase + r) = val;
        }
        return;
    }

    const int oh = (seg < 2);
    __half* Ch = (seg == 0) ? oq : ok;

    #pragma unroll
    for (int mf = 0; mf < 4; mf++) {
        const int r0 = mbase + warpM * 64 + mf * 16 + gid;
        #pragma unroll
        for (int nf = 0; nf < 4; nf++) {
            const int col = nbase + warpN * 32 + nf * 8 + tig * 2;
            const int cl = col & (DIM - 1);
            const float bz0 = __ldg(bias + cl);
            const float bz1 = __ldg(bias + cl + 1);
            const float v0 = acc[mf][nf][0] + bz0;
            const float v1 = acc[mf][nf][1] + bz1;
            const float v2 = acc[mf][nf][2] + bz0;
            const float v3 = acc[mf][nf][3] + bz1;
            if (oh) {
                *(__half2*)(Ch + (size_t)r0 * DIM + cl)       = __floats2half2_rn(v0, v1);
                *(__half2*)(Ch + (size_t)(r0 + 8) * DIM + cl) = __floats2half2_rn(v2, v3);
            } else {
                *(float2*)(oxr + (size_t)r0 * DIM + cl)       = make_float2(v0, v1);
                *(float2*)(oxr + (size_t)(r0 + 8) * DIM + cl) = make_float2(v2, v3);
            }
        }
    }
}

// =============== x -> fp16 copy ===============
__global__ void __launch_bounds__(256)
half_copy(const float* __restrict__ in, __half* __restrict__ out, int n8)
{
    int i = blockIdx.x * 256 + threadIdx.x;
    if (i < n8) {
        float4 f0 = ((const float4*)in)[2 * i];
        float4 f1 = ((const float4*)in)[2 * i + 1];
        __half2 h0 = __floats2half2_rn(f0.x, f0.y);
        __half2 h1 = __floats2half2_rn(f0.z, f0.w);
        __half2 h2 = __floats2half2_rn(f1.x, f1.y);
        __half2 h3 = __floats2half2_rn(f1.z, f1.w);
        uint4 o;
        o.x = *(uint32_t*)&h0; o.y = *(uint32_t*)&h1;
        o.z = *(uint32_t*)&h2; o.w = *(uint32_t*)&h3;
        ((uint4*)out)[i] = o;
    }
}

// =============== batched transpose of 4 DIM x DIM weights -> fp16 concat ===============
__global__ void __launch_bounds__(256)
transpose4_h(const float* __restrict__ w0, const float* __restrict__ w1,
             const float* __restrict__ w2, const float* __restrict__ w3,
             __half* __restrict__ out)
{
    const float* srcs[4] = {w0, w1, w2, w3};
    const float* in = srcs[blockIdx.z];
    __half* o = out + (size_t)blockIdx.z * DIM * DIM;

    __shared__ float t[32][33];
    const int bx = blockIdx.x * 32, by = blockIdx.y * 32;
    const int txx = threadIdx.x, tyy = threadIdx.y;
    #pragma unroll
    for (int i = tyy; i < 32; i += 8)
        t[i][txx] = in[(size_t)(by + i) * DIM + bx + txx];
    __syncthreads();
    #pragma unroll
    for (int i = tyy; i < 32; i += 8)
        o[(size_t)(bx + i) * DIM + by + txx] = __float2half_rn(t[txx][i]);
}

// =============== generic transpose fp32 -> fp16 ===============
__global__ void __launch_bounds__(256)
transpose_h(const float* __restrict__ in, __half* __restrict__ out, int R, int C)
{
    __shared__ float t[32][33];
    const int bx = blockIdx.x * 32, by = blockIdx.y * 32;
    const int txx = threadIdx.x, tyy = threadIdx.y;
    #pragma unroll
    for (int i = tyy; i < 32; i += 8) {
        int y = by + i, x = bx + txx;
        if (y < R && x < C) t[i][txx] = in[(size_t)y * C + x];
    }
    __syncthreads();
    #pragma unroll
    for (int i = tyy; i < 32; i += 8) {
        int oy = bx + i, ox = by + txx;
        if (oy < C && ox < R) out[(size_t)oy * R + ox] = __float2half_rn(t[txx][i]);
    }
}

// =============== rowsum reduction ===============
__global__ void __launch_bounds__(256)
reduce_rowsum(const float* __restrict__ part, float* __restrict__ rowsum)
{
    const int r = blockIdx.x * 256 + threadIdx.x;
    float s = 0.f;
    #pragma unroll
    for (int b = 0; b < 64; b++) s += part[(size_t)b * N_ROWS + r];
    rowsum[r] = s;
}

// =============== beta gate + mix -> fp16 m, one block per row ===============
__global__ void __launch_bounds__(256)
beta_mix(const float* __restrict__ a, const float* __restrict__ xr,
         const float* __restrict__ Wb, const float* __restrict__ bb,
         __half* __restrict__ Mout)
{
    const int row = blockIdx.x;
    const int tid = threadIdx.x;
    const float* ap = a  + (size_t)row * DIM;
    const float* xp = xr + (size_t)row * DIM;

    float partial = 0.f;
    #pragma unroll
    for (int i = tid; i < DIM; i += 256) {
        float av = ap[i], xv = xp[i];
        partial += av * Wb[i] + xv * Wb[DIM + i] + (av - xv) * Wb[2 * DIM + i];
    }
    __shared__ float red[8];
    #pragma unroll
    for (int o = 16; o > 0; o >>= 1) partial += __shfl_xor_sync(0xffffffffu, partial, o);
    if ((tid & 31) == 0) red[tid >> 5] = partial;
    __syncthreads();
    __shared__ float s_beta;
    if (tid == 0) {
        float t = 0.f;
        #pragma unroll
        for (int w = 0; w < 8; w++) t += red[w];
        t += bb[0];
        s_beta = 1.f / (1.f + expf(-t));
    }
    __syncthreads();
    const float beta = s_beta;
    __half* mp = Mout + (size_t)row * DIM;
    #pragma unroll
    for (int i = tid; i < DIM; i += 256)
        mp[i] = __float2half_rn(beta * xp[i] + (1.f - beta) * ap[i]);
}

// =============== launch ===============
extern "C" void kernel_launch(void* const* d_in, const int* in_sizes, int n_in,
                              void* d_out, int out_size)
{
    const float* x      = (const float*)d_in[0];
    const float* W_skip = (const float*)d_in[1];
    const float* b_skip = (const float*)d_in[2];
    const float* W_q    = (const float*)d_in[3];
    const float* b_q    = (const float*)d_in[4];
    const float* W_k    = (const float*)d_in[5];
    const float* b_k    = (const float*)d_in[6];
    const float* W_v    = (const float*)d_in[7];
    const float* b_v    = (const float*)d_in[8];
    const float* W_beta = (const float*)d_in[9];
    const float* b_beta = (const float*)d_in[10];
    const float* W_fc   = (const float*)d_in[11];
    const float* b_fc   = (const float*)d_in[12];
    float* out = (float*)d_out;

    __half *xh, *qh, *kh, *mh, *vTh, *Sh, *WcatT, *WfcT;
    float *xr, *a, *part, *rowsum;
    cudaGetSymbolAddress((void**)&xh,  g_xh);
    cudaGetSymbolAddress((void**)&qh,  g_qh);
    cudaGetSymbolAddress((void**)&kh,  g_kh);
    cudaGetSymbolAddress((void**)&xr,  g_xr);
    cudaGetSymbolAddress((void**)&a,   g_a);
    cudaGetSymbolAddress((void**)&mh,  g_mh);
    cudaGetSymbolAddress((void**)&vTh, g_vTh);
    cudaGetSymbolAddress((void**)&Sh,  g_Sh);
    cudaGetSymbolAddress((void**)&part,   g_part);
    cudaGetSymbolAddress((void**)&rowsum, g_rowsum);
    cudaGetSymbolAddress((void**)&WcatT, g_WcatT);
    cudaGetSymbolAddress((void**)&WfcT,  g_WfcT);

    cudaFuncSetAttribute(gemm_h,     cudaFuncAttributeMaxDynamicSharedMemorySize, DYN_SMEM);
    cudaFuncSetAttribute(gemm_proj4, cudaFuncAttributeMaxDynamicSharedMemorySize, DYN_SMEM);

    const dim3 tb(32, 8);
    const dim3 blk(256);
    const dim3 gProj4(4 * DIM / BN, N_ROWS / BM);       // (32, 64)
    const dim3 gAv(DIM / BN, N_ROWS / BM);              // (8, 64)
    const dim3 gScore(N_ROWS / BN, N_ROWS / BM);        // (64, 64)
    const dim3 gFc((NCLS + BN - 1) / BN, N_ROWS / BM);  // (8, 64)

    // ncu (-s 5 -c 1) captures the attn@v GEMM (index 5) this round
    half_copy<<<(N_ROWS * DIM / 8 + 255) / 256, 256>>>(x, xh, N_ROWS * DIM / 8);      // 0
    transpose4_h<<<dim3(32, 32, 4), tb>>>(W_q, W_k, W_v, W_skip, WcatT);              // 1
    transpose_h<<<dim3((NCLS + 31) / 32, 32), tb>>>(W_fc, WfcT, DIM, NCLS);           // 2
    gemm_proj4<<<gProj4, blk, DYN_SMEM>>>(xh, WcatT, b_q, b_k, b_v, b_skip,
                                          qh, kh, vTh, xr, 4 * DIM, DIM);             // 3
    gemm_h<<<gScore, blk, DYN_SMEM>>>(qh, kh, nullptr, Sh, 1, 1.f / 32.f,
                                      N_ROWS, N_ROWS, DIM, N_ROWS, 1, part);          // 4
    reduce_rowsum<<<N_ROWS / 256, 256>>>(part, rowsum);                               // 5 <- ncu... small
    gemm_h<<<gAv, blk, DYN_SMEM>>>(Sh, vTh, nullptr, a, 0, 1.f,
                                   DIM, DIM, N_ROWS, DIM, 2, rowsum);

    beta_mix<<<N_ROWS, 256>>>(a, xr, W_beta, b_beta, mh);

    gemm_h<<<gFc, blk, DYN_SMEM>>>(mh, WfcT, b_fc, out, 0, 1.f,
                                   NCLS, NCLS, DIM, NCLS, 0, nullptr);
}